// round 10
// baseline (speedup 1.0000x reference)
#include <cuda_runtime.h>
#include <cuda_bf16.h>
#include <mma.h>
#include <cstdint>

using namespace nvcuda;

// Problem constants
#define SS_   128     // MSA depth S  (K of GEMM1)
#define NRES  256     // residues
#define DD    64      // msa dim
#define HH_   32      // proj dim H
#define M_TOT 8192    // N*H
#define KK2   1024    // H*H (K of GEMM2)

// ---------------- device scratch (allocation-free rule) ----------------
__device__ float g_A[SS_ * M_TOT];                  // [s][m] fp32 (prep out)
__device__ float g_B[SS_ * M_TOT];
__device__ __nv_bfloat16 g_Ah[M_TOT * SS_];         // [m][s] K-major bf16 hi/lo
__device__ __nv_bfloat16 g_Al[M_TOT * SS_];
__device__ __nv_bfloat16 g_Bh[M_TOT * SS_];
__device__ __nv_bfloat16 g_Bl[M_TOT * SS_];
// Wo^T packed as 16x16 col-major fragment tiles: [kt(64)][nf(4)] -> 256 elems
__device__ __nv_bfloat16 g_Wph[64 * 4 * 256];       // 128 KB
__device__ __nv_bfloat16 g_Wpl[64 * 4 * 256];       // 128 KB
__device__ float g_invden[NRES];

__device__ __forceinline__ void split_bf16(float v, __nv_bfloat16& h, __nv_bfloat16& l) {
    h = __float2bfloat16(v);
    l = __float2bfloat16(v - __bfloat162float(h));
}

__device__ __forceinline__ void cpa16(void* s, const void* g) {
    uint32_t sa = (uint32_t)__cvta_generic_to_shared(s);
    asm volatile("cp.async.cg.shared.global [%0], [%1], 16;" :: "r"(sa), "l"(g));
}
__device__ __forceinline__ void cpa_commit() {
    asm volatile("cp.async.commit_group;" ::: "memory");
}
template <int N>
__device__ __forceinline__ void cpa_wait() {
    asm volatile("cp.async.wait_group %0;" :: "n"(N) : "memory");
}

// ---------------- combo: Wo fragment-tile pack + denom ----------------
__global__ void __launch_bounds__(256) k_combo(const float* __restrict__ mask,
                                               const float* __restrict__ Wo) {
    int idx = blockIdx.x * 256 + threadIdx.x;     // 65536
    int tile = idx >> 8;          // kt*4+nf
    int within = idx & 255;       // n*16+k
    int kt = tile >> 2, nf = tile & 3;
    int n = within >> 4, k = within & 15;
    int c = kt * 16 + k, p = nf * 16 + n;
    float v = Wo[(size_t)c * 64 + p];
    __nv_bfloat16 h, l; split_bf16(v, h, l);
    g_Wph[idx] = h;
    g_Wpl[idx] = l;

    if (blockIdx.x == 0) {
        int i = threadIdx.x;
        float s = 0.f;
        #pragma unroll 8
        for (int t = 0; t < SS_; ++t) s += mask[t * NRES + i];
        g_invden[i] = 1.0f / fmaxf(s, 1.0f);
    }
}

// ---------------- prep: LN + dual projection + mask + denom fold ----------------
__global__ void __launch_bounds__(256) k_prep(
    const float* __restrict__ x, const float* __restrict__ mask,
    const float* __restrict__ gamma, const float* __restrict__ beta,
    const float* __restrict__ Wa, const float* __restrict__ ba,
    const float* __restrict__ Wb, const float* __restrict__ bb)
{
    __shared__ float sx[8][64];
    int warp = threadIdx.x >> 5, lane = threadIdx.x & 31;
    int row = blockIdx.x * 8 + warp;          // row = s*256 + i
    const float* xr = x + (size_t)row * DD;

    float v0 = xr[lane], v1 = xr[lane + 32];
    float sum = v0 + v1;
    #pragma unroll
    for (int o = 16; o; o >>= 1) sum += __shfl_xor_sync(~0u, sum, o);
    float mu = sum * (1.0f / 64.0f);
    float d0 = v0 - mu, d1 = v1 - mu;
    float vs = d0 * d0 + d1 * d1;
    #pragma unroll
    for (int o = 16; o; o >>= 1) vs += __shfl_xor_sync(~0u, vs, o);
    float rstd = rsqrtf(vs * (1.0f / 64.0f) + 1e-5f);
    sx[warp][lane]      = d0 * rstd * gamma[lane]      + beta[lane];
    sx[warp][lane + 32] = d1 * rstd * gamma[lane + 32] + beta[lane + 32];
    __syncwarp();

    int s = row >> 8, i = row & 255;
    float m = mask[s * NRES + i];
    float a = ba[lane], b = bb[lane];
    #pragma unroll
    for (int d = 0; d < 64; ++d) {
        float xv = sx[warp][d];
        a = fmaf(xv, Wa[d * HH_ + lane], a);
        b = fmaf(xv, Wb[d * HH_ + lane], b);
    }
    a *= m * g_invden[i];
    b *= m;
    g_A[s * M_TOT + i * HH_ + lane] = a;
    g_B[s * M_TOT + i * HH_ + lane] = b;
}

// ---------------- transpose + split: fp32 [s][m] -> bf16 hi/lo [m][s] ----------------
__global__ void k_split_t() {
    __shared__ float t[32][33];
    const float* src = blockIdx.z ? g_B : g_A;
    __nv_bfloat16* oh = blockIdx.z ? g_Bh : g_Ah;
    __nv_bfloat16* ol = blockIdx.z ? g_Bl : g_Al;
    int tx = threadIdx.x, ty = threadIdx.y;
    #pragma unroll
    for (int k = 0; k < 4; ++k) {
        int s = blockIdx.y * 32 + ty + k * 8;
        int m = blockIdx.x * 32 + tx;
        t[ty + k * 8][tx] = src[(size_t)s * M_TOT + m];
    }
    __syncthreads();
    #pragma unroll
    for (int k = 0; k < 4; ++k) {
        int m = blockIdx.x * 32 + ty + k * 8;
        int s = blockIdx.y * 32 + tx;
        float v = t[tx][ty + k * 8];
        __nv_bfloat16 h, l; split_bf16(v, h, l);
        oh[(size_t)m * SS_ + s] = h;
        ol[(size_t)m * SS_ + s] = l;
    }
}

// ===================== FUSED: 128(m)x256(n) outer-GEMM tile + @Wo epilogue =====================
// 512 threads, 16 warps as 4(m)x4(n); warp tile 32x64 (same as R8).
// Epilogue covers 32 complete GEMM2 rows; run as two 16-row halves (warps 0-7 / 8-15).
#define SKC 40
#define STAGE_B ((128 + 128 + 256 + 256) * SKC * 2)   // 61440 B per stage
#define AE_LD 1032
// smem (bytes):
//   Mainloop: stage0 [0,61440) | stage1 [61440,122880)
//   Epilogue: sAe_h [0,66048) | sAe_l [66048,132096)  (32 rows x 1032)
//             scratch [132096,148480)  (16 warps x 1 KB, convert phase)
//             partials [132096,197632) (2 halves x 8 warps x 16x64 fp32)
#define OFF_SCR 132096
#define SMF 197632

__global__ void __launch_bounds__(512, 1) k_fused(const float* __restrict__ bo,
                                                  float* __restrict__ out) {
    extern __shared__ char smc[];
    int tid = threadIdx.x;
    int wid = tid >> 5, lane = tid & 31;
    int wm = wid & 3, wn = wid >> 2;   // warp tile 32(m) x 64(n), wn in [0,4)
    int bm = blockIdx.x, bn = blockIdx.y;

    const __nv_bfloat16* gAh = g_Ah + (size_t)bm * 128 * SS_;
    const __nv_bfloat16* gAl = g_Al + (size_t)bm * 128 * SS_;
    const __nv_bfloat16* gBh = g_Bh + (size_t)bn * 256 * SS_;
    const __nv_bfloat16* gBl = g_Bl + (size_t)bn * 256 * SS_;

    wmma::fragment<wmma::accumulator, 16, 16, 16, float> acc[2][4];
    #pragma unroll
    for (int i = 0; i < 2; ++i)
        #pragma unroll
        for (int j = 0; j < 4; ++j) wmma::fill_fragment(acc[i][j], 0.0f);

    auto load_stage = [&](int stage, int ch) {
        char* base = smc + stage * STAGE_B;
        __nv_bfloat16* dAh = (__nv_bfloat16*)base;
        __nv_bfloat16* dAl = dAh + 128 * SKC;
        __nv_bfloat16* dBh = dAl + 128 * SKC;
        __nv_bfloat16* dBl = dBh + 256 * SKC;
        int kb = ch * 32;
        {   // A: 128 rows x 4 segs = 512 segs, one per thread
            int row = tid >> 2, seg = tid & 3;
            size_t go = (size_t)row * SS_ + kb + seg * 8;
            int so = row * SKC + seg * 8;
            cpa16(dAh + so, gAh + go);
            cpa16(dAl + so, gAl + go);
        }
        #pragma unroll
        for (int it = 0; it < 2; ++it) {   // B: 256 rows x 4 segs = 1024 segs
            int idx = it * 512 + tid;
            int row = idx >> 2, seg = idx & 3;
            size_t go = (size_t)row * SS_ + kb + seg * 8;
            int so = row * SKC + seg * 8;
            cpa16(dBh + so, gBh + go);
            cpa16(dBl + so, gBl + go);
        }
        cpa_commit();
    };

    // ---------------- Phase 1: pipelined mainloop (R8 MMA schedule) ----------------
    load_stage(0, 0);
    #pragma unroll
    for (int ch = 0; ch < 4; ++ch) {
        int cur = ch & 1;
        if (ch < 3) load_stage(cur ^ 1, ch + 1);
        if (ch < 3) cpa_wait<1>(); else cpa_wait<0>();
        __syncthreads();

        char* base = smc + cur * STAGE_B;
        __nv_bfloat16* sAh = (__nv_bfloat16*)base;
        __nv_bfloat16* sAl = sAh + 128 * SKC;
        __nv_bfloat16* sBh = sAl + 128 * SKC;
        __nv_bfloat16* sBl = sBh + 256 * SKC;

        #pragma unroll
        for (int ks = 0; ks < 2; ++ks) {
            wmma::fragment<wmma::matrix_a, 16, 16, 16, __nv_bfloat16, wmma::row_major> ah[2], al[2];
            #pragma unroll
            for (int mf = 0; mf < 2; ++mf) {
                wmma::load_matrix_sync(ah[mf], sAh + (wm * 32 + mf * 16) * SKC + ks * 16, SKC);
                wmma::load_matrix_sync(al[mf], sAl + (wm * 32 + mf * 16) * SKC + ks * 16, SKC);
            }
            #pragma unroll
            for (int nf = 0; nf < 4; ++nf) {
                wmma::fragment<wmma::matrix_b, 16, 16, 16, __nv_bfloat16, wmma::col_major> bh, bl;
                wmma::load_matrix_sync(bh, sBh + (wn * 64 + nf * 16) * SKC + ks * 16, SKC);
                wmma::mma_sync(acc[0][nf], ah[0], bh, acc[0][nf]);
                wmma::mma_sync(acc[1][nf], ah[1], bh, acc[1][nf]);
                wmma::mma_sync(acc[0][nf], al[0], bh, acc[0][nf]);
                wmma::mma_sync(acc[1][nf], al[1], bh, acc[1][nf]);
                wmma::load_matrix_sync(bl, sBl + (wn * 64 + nf * 16) * SKC + ks * 16, SKC);
                wmma::mma_sync(acc[0][nf], ah[0], bl, acc[0][nf]);
                wmma::mma_sync(acc[1][nf], ah[1], bl, acc[1][nf]);
            }
        }
        __syncthreads();
    }

    // ---------------- Phase 2a: convert frags -> sAe hi/lo [32][1024] ----------------
    // frag (wm,wn,mf,nf): row r = wm*8 + wn*2 + (nf>>1) in [0,32);
    // col c = (mf*16+hr)*32 + (nf&1)*16 + kc  =  mf*512 + hr*32 + (nf&1)*16 + kc
    __nv_bfloat16* sAe_h = (__nv_bfloat16*)smc;
    __nv_bfloat16* sAe_l = sAe_h + 32 * AE_LD;
    float* sScr  = (float*)(smc + OFF_SCR);
    float* sPart = (float*)(smc + OFF_SCR);
    {
        float* scr = sScr + wid * 256;
        int hr = lane >> 1, kc0 = (lane & 1) * 8;
        #pragma unroll
        for (int mf = 0; mf < 2; ++mf)
            #pragma unroll
            for (int nf = 0; nf < 4; ++nf) {
                wmma::store_matrix_sync(scr, acc[mf][nf], 16, wmma::mem_row_major);
                __syncwarp();
                const float* p = scr + hr * 16 + kc0;
                uint32_t hp[4], lp[4];
                #pragma unroll
                for (int q = 0; q < 4; ++q) {
                    __nv_bfloat16 h0, l0, h1, l1;
                    split_bf16(p[2 * q], h0, l0);
                    split_bf16(p[2 * q + 1], h1, l1);
                    hp[q] = (uint32_t)__bfloat16_as_ushort(h0) | ((uint32_t)__bfloat16_as_ushort(h1) << 16);
                    lp[q] = (uint32_t)__bfloat16_as_ushort(l0) | ((uint32_t)__bfloat16_as_ushort(l1) << 16);
                }
                int r = wm * 8 + wn * 2 + (nf >> 1);
                int c = mf * 512 + hr * 32 + (nf & 1) * 16 + kc0;
                *(uint4*)(sAe_h + r * AE_LD + c) = make_uint4(hp[0], hp[1], hp[2], hp[3]);
                *(uint4*)(sAe_l + r * AE_LD + c) = make_uint4(lp[0], lp[1], lp[2], lp[3]);
                __syncwarp();
            }
    }
    __syncthreads();

    // ---------------- Phase 2b: two 16-row half-epilogues (warps 0-7 / 8-15) ----------------
    {
        int hw = wid >> 3;             // half (row group 16)
        int lw = wid & 7;              // warp within half: kt slice of 8
        wmma::fragment<wmma::accumulator, 16, 16, 16, float> acc2[4];
        #pragma unroll
        for (int j = 0; j < 4; ++j) wmma::fill_fragment(acc2[j], 0.0f);

        #pragma unroll
        for (int ks = 0; ks < 8; ++ks) {
            int kt = lw * 8 + ks;
            int kk = kt * 16;
            wmma::fragment<wmma::matrix_b, 16, 16, 16, __nv_bfloat16, wmma::col_major> bh[4], bl[4];
            #pragma unroll
            for (int nf = 0; nf < 4; ++nf) {
                wmma::load_matrix_sync(bh[nf], g_Wph + (kt * 4 + nf) * 256, 16);
                wmma::load_matrix_sync(bl[nf], g_Wpl + (kt * 4 + nf) * 256, 16);
            }
            wmma::fragment<wmma::matrix_a, 16, 16, 16, __nv_bfloat16, wmma::row_major> ah, al;
            wmma::load_matrix_sync(ah, sAe_h + hw * 16 * AE_LD + kk, AE_LD);
            wmma::load_matrix_sync(al, sAe_l + hw * 16 * AE_LD + kk, AE_LD);
            #pragma unroll
            for (int nf = 0; nf < 4; ++nf) wmma::mma_sync(acc2[nf], ah, bh[nf], acc2[nf]);
            #pragma unroll
            for (int nf = 0; nf < 4; ++nf) wmma::mma_sync(acc2[nf], al, bh[nf], acc2[nf]);
            #pragma unroll
            for (int nf = 0; nf < 4; ++nf) wmma::mma_sync(acc2[nf], ah, bl[nf], acc2[nf]);
        }
        __syncthreads();               // sAe reads done before partials overwrite scratch zone
        #pragma unroll
        for (int nf = 0; nf < 4; ++nf)
            wmma::store_matrix_sync(sPart + hw * 8192 + lw * 1024 + nf * 16,
                                    acc2[nf], 64, wmma::mem_row_major);
    }
    __syncthreads();

    // ---------------- Phase 2c: reduce 8 partials per half, +bo, store ----------------
    {
        int row = tid >> 4;            // 0..31
        int p4  = (tid & 15) * 4;
        int hw = row >> 4, r16 = row & 15;
        const float* basep = sPart + hw * 8192 + r16 * 64 + p4;
        float4 s = *(const float4*)basep;
        #pragma unroll
        for (int w = 1; w < 8; ++w) {
            float4 v = *(const float4*)(basep + w * 1024);
            s.x += v.x; s.y += v.y; s.z += v.z; s.w += v.w;
        }
        float4 bv = __ldg((const float4*)(bo + p4));
        s.x += bv.x; s.y += bv.y; s.z += bv.z; s.w += bv.w;
        size_t rg = (size_t)(bm * 4 + (row >> 3)) * 256 + bn * 8 + (row & 7);
        *(float4*)(out + rg * 64 + p4) = s;
    }
}

extern "C" void kernel_launch(void* const* d_in, const int* in_sizes, int n_in,
                              void* d_out, int out_size) {
    const float* msa   = (const float*)d_in[0];
    const float* mask  = (const float*)d_in[1];
    const float* gamma = (const float*)d_in[2];
    const float* beta  = (const float*)d_in[3];
    const float* Wa    = (const float*)d_in[4];
    const float* ba    = (const float*)d_in[5];
    const float* Wb    = (const float*)d_in[6];
    const float* bb    = (const float*)d_in[7];
    const float* Wo    = (const float*)d_in[8];
    const float* bo    = (const float*)d_in[9];
    float* out = (float*)d_out;

    cudaFuncSetAttribute(k_fused, cudaFuncAttributeMaxDynamicSharedMemorySize, SMF);

    // order so k_fused is the 4th launch (profiled slot)
    k_combo<<<256, 256>>>(mask, Wo);
    k_prep<<<4096, 256>>>(msa, mask, gamma, beta, Wa, ba, Wb, bb);
    k_split_t<<<dim3(256, 4, 2), dim3(32, 8)>>>();
    k_fused<<<dim3(64, 32), 512, SMF>>>(bo, out);
}

// round 11
// speedup vs baseline: 1.2651x; 1.2651x over previous
#include <cuda_runtime.h>
#include <cuda_bf16.h>
#include <mma.h>
#include <cstdint>

using namespace nvcuda;

// Problem constants
#define SS_   128     // MSA depth S  (K of GEMM1)
#define NRES  256     // residues
#define DD    64      // msa dim
#define HH_   32      // proj dim H
#define M_TOT 8192    // N*H
#define KK2   1024    // H*H (K of GEMM2)

// ---------------- device scratch (allocation-free rule) ----------------
__device__ __align__(16) float g_A[SS_ * M_TOT];
__device__ __align__(16) float g_B[SS_ * M_TOT];
__device__ __align__(16) __nv_bfloat16 g_Ah[M_TOT * SS_];   // [m][s] K-major bf16 hi/lo
__device__ __align__(16) __nv_bfloat16 g_Al[M_TOT * SS_];
__device__ __align__(16) __nv_bfloat16 g_Bh[M_TOT * SS_];
__device__ __align__(16) __nv_bfloat16 g_Bl[M_TOT * SS_];
// Wo^T packed FRAG-LINEAR per 16x16 tile: [tile=kt*4+nf][lane][8 bf16]
// lane's 8 elems = {B[2c][n],B[2c+1][n],B[2c+8][n],B[2c+9][n],  (n8 block 0)
//                   B[2c][n+8],B[2c+1][n+8],B[2c+8][n+8],B[2c+9][n+8]}  (block 1)
// with n = lane/4, c = lane%4, B[k][nn] = Wo[(kt*16+k)*64 + nf*16+nn]
__device__ __align__(16) __nv_bfloat16 g_Wph[64 * 4 * 256];  // 128 KB
__device__ __align__(16) __nv_bfloat16 g_Wpl[64 * 4 * 256];  // 128 KB
__device__ float g_invden[NRES];

__device__ __forceinline__ void split_bf16(float v, __nv_bfloat16& h, __nv_bfloat16& l) {
    h = __float2bfloat16(v);
    l = __float2bfloat16(v - __bfloat162float(h));
}

__device__ __forceinline__ void cpa16(void* s, const void* g) {
    uint32_t sa = (uint32_t)__cvta_generic_to_shared(s);
    asm volatile("cp.async.cg.shared.global [%0], [%1], 16;" :: "r"(sa), "l"(g));
}
__device__ __forceinline__ void cpa_commit() {
    asm volatile("cp.async.commit_group;" ::: "memory");
}
template <int N>
__device__ __forceinline__ void cpa_wait() {
    asm volatile("cp.async.wait_group %0;" :: "n"(N) : "memory");
}

#define MMA16816(D, A0, A1, A2, A3, B0, B1) \
    asm volatile("mma.sync.aligned.m16n8k16.row.col.f32.bf16.bf16.f32 " \
        "{%0,%1,%2,%3}, {%4,%5,%6,%7}, {%8,%9}, {%0,%1,%2,%3};" \
        : "+f"((D)[0]), "+f"((D)[1]), "+f"((D)[2]), "+f"((D)[3]) \
        : "r"(A0), "r"(A1), "r"(A2), "r"(A3), "r"(B0), "r"(B1))

// ---------------- combo: Wo frag-linear pack + denom ----------------
__global__ void __launch_bounds__(256) k_combo(const float* __restrict__ mask,
                                               const float* __restrict__ Wo) {
    int idx = blockIdx.x * 256 + threadIdx.x;     // 65536
    int tile = idx >> 8;          // kt*4+nf
    int within = idx & 255;       // lane*8+e
    int lane = within >> 3, e = within & 7;
    int kt = tile >> 2, nf = tile & 3;
    int n = (lane >> 2) + ((e >> 2) << 3);
    int cc = lane & 3;
    int k = 2 * cc + (e & 1) + (((e >> 1) & 1) << 3);
    float v = Wo[(size_t)(kt * 16 + k) * 64 + nf * 16 + n];
    __nv_bfloat16 h, l; split_bf16(v, h, l);
    g_Wph[idx] = h;
    g_Wpl[idx] = l;

    if (blockIdx.x == 0) {
        int i = threadIdx.x;
        float s = 0.f;
        #pragma unroll 8
        for (int t = 0; t < SS_; ++t) s += mask[t * NRES + i];
        g_invden[i] = 1.0f / fmaxf(s, 1.0f);
    }
}

// ---------------- prep: LN + dual projection + mask + denom fold ----------------
__global__ void __launch_bounds__(256) k_prep(
    const float* __restrict__ x, const float* __restrict__ mask,
    const float* __restrict__ gamma, const float* __restrict__ beta,
    const float* __restrict__ Wa, const float* __restrict__ ba,
    const float* __restrict__ Wb, const float* __restrict__ bb)
{
    __shared__ float sx[8][64];
    int warp = threadIdx.x >> 5, lane = threadIdx.x & 31;
    int row = blockIdx.x * 8 + warp;          // row = s*256 + i
    const float* xr = x + (size_t)row * DD;

    float v0 = xr[lane], v1 = xr[lane + 32];
    float sum = v0 + v1;
    #pragma unroll
    for (int o = 16; o; o >>= 1) sum += __shfl_xor_sync(~0u, sum, o);
    float mu = sum * (1.0f / 64.0f);
    float d0 = v0 - mu, d1 = v1 - mu;
    float vs = d0 * d0 + d1 * d1;
    #pragma unroll
    for (int o = 16; o; o >>= 1) vs += __shfl_xor_sync(~0u, vs, o);
    float rstd = rsqrtf(vs * (1.0f / 64.0f) + 1e-5f);
    sx[warp][lane]      = d0 * rstd * gamma[lane]      + beta[lane];
    sx[warp][lane + 32] = d1 * rstd * gamma[lane + 32] + beta[lane + 32];
    __syncwarp();

    int s = row >> 8, i = row & 255;
    float m = mask[s * NRES + i];
    float a = ba[lane], b = bb[lane];
    #pragma unroll
    for (int d = 0; d < 64; ++d) {
        float xv = sx[warp][d];
        a = fmaf(xv, Wa[d * HH_ + lane], a);
        b = fmaf(xv, Wb[d * HH_ + lane], b);
    }
    a *= m * g_invden[i];
    b *= m;
    g_A[s * M_TOT + i * HH_ + lane] = a;
    g_B[s * M_TOT + i * HH_ + lane] = b;
}

// ---------------- transpose + split: fp32 [s][m] -> bf16 hi/lo [m][s] ----------------
__global__ void k_split_t() {
    __shared__ float t[32][33];
    const float* src = blockIdx.z ? g_B : g_A;
    __nv_bfloat16* oh = blockIdx.z ? g_Bh : g_Ah;
    __nv_bfloat16* ol = blockIdx.z ? g_Bl : g_Al;
    int tx = threadIdx.x, ty = threadIdx.y;
    #pragma unroll
    for (int k = 0; k < 4; ++k) {
        int s = blockIdx.y * 32 + ty + k * 8;
        int m = blockIdx.x * 32 + tx;
        t[ty + k * 8][tx] = src[(size_t)s * M_TOT + m];
    }
    __syncthreads();
    #pragma unroll
    for (int k = 0; k < 4; ++k) {
        int m = blockIdx.x * 32 + ty + k * 8;
        int s = blockIdx.y * 32 + tx;
        float v = t[tx][ty + k * 8];
        __nv_bfloat16 h, l; split_bf16(v, h, l);
        oh[(size_t)m * SS_ + s] = h;
        ol[(size_t)m * SS_ + s] = l;
    }
}

// ===================== FUSED: outer-GEMM (128x128 tile) + @Wo epilogue =====================
#define SKC 40
#define TILE_B (128 * SKC * 2)
#define STAGE_B (4 * TILE_B)          // 40960 B per stage
#define AE_LD 1032
#define SMF 98816

__global__ void __launch_bounds__(256, 2) k_fused(const float* __restrict__ bo,
                                                  float* __restrict__ out) {
    extern __shared__ char smc[];
    int tid = threadIdx.x;
    int wid = tid >> 5, lane = tid & 31;
    int wm = wid & 3, wn = wid >> 2;   // warp tile 32(m) x 64(n)
    int bm = blockIdx.x, bn = blockIdx.y;

    const __nv_bfloat16* gAh = g_Ah + (size_t)bm * 128 * SS_;
    const __nv_bfloat16* gAl = g_Al + (size_t)bm * 128 * SS_;
    const __nv_bfloat16* gBh = g_Bh + (size_t)bn * 128 * SS_;
    const __nv_bfloat16* gBl = g_Bl + (size_t)bn * 128 * SS_;

    wmma::fragment<wmma::accumulator, 16, 16, 16, float> acc[2][4];
    #pragma unroll
    for (int i = 0; i < 2; ++i)
        #pragma unroll
        for (int j = 0; j < 4; ++j) wmma::fill_fragment(acc[i][j], 0.0f);

    auto load_stage = [&](int stage, int ch) {
        char* base = smc + stage * STAGE_B;
        __nv_bfloat16* dAh = (__nv_bfloat16*)base;
        __nv_bfloat16* dAl = dAh + 128 * SKC;
        __nv_bfloat16* dBh = dAl + 128 * SKC;
        __nv_bfloat16* dBl = dBh + 128 * SKC;
        int kb = ch * 32;
        #pragma unroll
        for (int it = 0; it < 2; ++it) {
            int idx = it * 256 + tid;
            int row = idx >> 2, seg = idx & 3;
            size_t go = (size_t)row * SS_ + kb + seg * 8;
            int so = row * SKC + seg * 8;
            cpa16(dAh + so, gAh + go);
            cpa16(dAl + so, gAl + go);
            cpa16(dBh + so, gBh + go);
            cpa16(dBl + so, gBl + go);
        }
        cpa_commit();
    };

    // ---------------- Phase 1: pipelined mainloop (R8 schedule) ----------------
    load_stage(0, 0);
    #pragma unroll
    for (int ch = 0; ch < 4; ++ch) {
        int cur = ch & 1;
        if (ch < 3) load_stage(cur ^ 1, ch + 1);
        if (ch < 3) cpa_wait<1>(); else cpa_wait<0>();
        __syncthreads();

        char* base = smc + cur * STAGE_B;
        __nv_bfloat16* sAh = (__nv_bfloat16*)base;
        __nv_bfloat16* sAl = sAh + 128 * SKC;
        __nv_bfloat16* sBh = sAl + 128 * SKC;
        __nv_bfloat16* sBl = sBh + 128 * SKC;

        #pragma unroll
        for (int ks = 0; ks < 2; ++ks) {
            wmma::fragment<wmma::matrix_a, 16, 16, 16, __nv_bfloat16, wmma::row_major> ah[2], al[2];
            #pragma unroll
            for (int mf = 0; mf < 2; ++mf) {
                wmma::load_matrix_sync(ah[mf], sAh + (wm * 32 + mf * 16) * SKC + ks * 16, SKC);
                wmma::load_matrix_sync(al[mf], sAl + (wm * 32 + mf * 16) * SKC + ks * 16, SKC);
            }
            #pragma unroll
            for (int nf = 0; nf < 4; ++nf) {
                wmma::fragment<wmma::matrix_b, 16, 16, 16, __nv_bfloat16, wmma::col_major> bh, bl;
                wmma::load_matrix_sync(bh, sBh + (wn * 64 + nf * 16) * SKC + ks * 16, SKC);
                wmma::mma_sync(acc[0][nf], ah[0], bh, acc[0][nf]);
                wmma::mma_sync(acc[1][nf], ah[1], bh, acc[1][nf]);
                wmma::mma_sync(acc[0][nf], al[0], bh, acc[0][nf]);
                wmma::mma_sync(acc[1][nf], al[1], bh, acc[1][nf]);
                wmma::load_matrix_sync(bl, sBl + (wn * 64 + nf * 16) * SKC + ks * 16, SKC);
                wmma::mma_sync(acc[0][nf], ah[0], bl, acc[0][nf]);
                wmma::mma_sync(acc[1][nf], ah[1], bl, acc[1][nf]);
            }
        }
        __syncthreads();
    }

    // ---------------- Phase 2a: convert frags -> sAe hi/lo [16][1024] ----------------
    __nv_bfloat16* sAe_h = (__nv_bfloat16*)smc;
    __nv_bfloat16* sAe_l = sAe_h + 16 * AE_LD;
    float* sScr  = (float*)(smc + 66048);
    float* sPart = (float*)(smc + 66048);
    {
        float* scr = sScr + wid * 256;
        int hr = lane >> 1, kc0 = (lane & 1) * 8;
        #pragma unroll
        for (int mf = 0; mf < 2; ++mf)
            #pragma unroll
            for (int nf = 0; nf < 4; ++nf) {
                wmma::store_matrix_sync(scr, acc[mf][nf], 16, wmma::mem_row_major);
                __syncwarp();
                const float* p = scr + hr * 16 + kc0;
                uint32_t hp[4], lp[4];
                #pragma unroll
                for (int q = 0; q < 4; ++q) {
                    __nv_bfloat16 h0, l0, h1, l1;
                    split_bf16(p[2 * q], h0, l0);
                    split_bf16(p[2 * q + 1], h1, l1);
                    hp[q] = (uint32_t)__bfloat16_as_ushort(h0) | ((uint32_t)__bfloat16_as_ushort(h1) << 16);
                    lp[q] = (uint32_t)__bfloat16_as_ushort(l0) | ((uint32_t)__bfloat16_as_ushort(l1) << 16);
                }
                int r = wm * 4 + wn * 2 + (nf >> 1);
                int c = mf * 512 + hr * 32 + (nf & 1) * 16 + kc0;
                *(uint4*)(sAe_h + r * AE_LD + c) = make_uint4(hp[0], hp[1], hp[2], hp[3]);
                *(uint4*)(sAe_l + r * AE_LD + c) = make_uint4(lp[0], lp[1], lp[2], lp[3]);
                __syncwarp();
            }
    }
    __syncthreads();

    // ---------------- Phase 2b: C16x64 = sAe @ Wo  (PTX mma, frag-linear Wo via LDG.128) ----------------
    {
        float d[4][2][4];          // [nf][n8-block][reg]
        #pragma unroll
        for (int a = 0; a < 4; ++a)
            #pragma unroll
            for (int b = 0; b < 2; ++b)
                #pragma unroll
                for (int e = 0; e < 4; ++e) d[a][b][e] = 0.f;

        int g = lane >> 2, cg = lane & 3;                         // groupID, threadInGroup
        int lrow  = (lane & 7) + ((lane >> 3) & 1) * 8;           // ldmatrix row per lane
        int lcol8 = (lane >> 4) * 8;                              // k-half select

        #pragma unroll
        for (int ks = 0; ks < 8; ++ks) {
            int kt = wid * 8 + ks;
            int kk = kt * 16;
            uint32_t ah0, ah1, ah2, ah3, al0, al1, al2, al3;
            uint32_t adh = (uint32_t)__cvta_generic_to_shared(sAe_h + lrow * AE_LD + kk + lcol8);
            uint32_t adl = (uint32_t)__cvta_generic_to_shared(sAe_l + lrow * AE_LD + kk + lcol8);
            asm volatile("ldmatrix.sync.aligned.m8n8.x4.shared.b16 {%0,%1,%2,%3}, [%4];"
                         : "=r"(ah0), "=r"(ah1), "=r"(ah2), "=r"(ah3) : "r"(adh));
            asm volatile("ldmatrix.sync.aligned.m8n8.x4.shared.b16 {%0,%1,%2,%3}, [%4];"
                         : "=r"(al0), "=r"(al1), "=r"(al2), "=r"(al3) : "r"(adl));
            #pragma unroll
            for (int nf = 0; nf < 4; ++nf) {
                uint4 vh = ((const uint4*)g_Wph)[(size_t)(kt * 4 + nf) * 32 + lane];
                uint4 vl = ((const uint4*)g_Wpl)[(size_t)(kt * 4 + nf) * 32 + lane];
                MMA16816(d[nf][0], ah0, ah1, ah2, ah3, vh.x, vh.y);
                MMA16816(d[nf][1], ah0, ah1, ah2, ah3, vh.z, vh.w);
                MMA16816(d[nf][0], al0, al1, al2, al3, vh.x, vh.y);
                MMA16816(d[nf][1], al0, al1, al2, al3, vh.z, vh.w);
                MMA16816(d[nf][0], ah0, ah1, ah2, ah3, vl.x, vl.y);
                MMA16816(d[nf][1], ah0, ah1, ah2, ah3, vl.z, vl.w);
            }
        }
        __syncthreads();          // all sAe reads done (sPart region disjoint, keep order)

        // store partials with documented D layout: d0,d1 -> (row g, cols 2cg,2cg+1); d2,d3 -> row g+8
        #pragma unroll
        for (int nf = 0; nf < 4; ++nf)
            #pragma unroll
            for (int blk = 0; blk < 2; ++blk) {
                int col = nf * 16 + blk * 8 + cg * 2;
                float* p0 = sPart + wid * 1024 + g * 64 + col;
                p0[0] = d[nf][blk][0]; p0[1] = d[nf][blk][1];
                float* p1 = sPart + wid * 1024 + (g + 8) * 64 + col;
                p1[0] = d[nf][blk][2]; p1[1] = d[nf][blk][3];
            }
    }
    __syncthreads();

    // ---------------- Phase 2c: reduce 8 partials, +bo, store ----------------
    {
        int row = tid >> 4;            // 0..15
        int p4  = (tid & 15) * 4;
        float4 s = *(float4*)(sPart + row * 64 + p4);
        #pragma unroll
        for (int w = 1; w < 8; ++w) {
            float4 v = *(float4*)(sPart + w * 1024 + row * 64 + p4);
            s.x += v.x; s.y += v.y; s.z += v.z; s.w += v.w;
        }
        float4 bv = __ldg((const float4*)(bo + p4));
        s.x += bv.x; s.y += bv.y; s.z += bv.z; s.w += bv.w;
        size_t rg = (size_t)(bm * 4 + (row >> 2)) * 256 + bn * 4 + (row & 3);
        *(float4*)(out + rg * 64 + p4) = s;
    }
}

extern "C" void kernel_launch(void* const* d_in, const int* in_sizes, int n_in,
                              void* d_out, int out_size) {
    const float* msa   = (const float*)d_in[0];
    const float* mask  = (const float*)d_in[1];
    const float* gamma = (const float*)d_in[2];
    const float* beta  = (const float*)d_in[3];
    const float* Wa    = (const float*)d_in[4];
    const float* ba    = (const float*)d_in[5];
    const float* Wb    = (const float*)d_in[6];
    const float* bb    = (const float*)d_in[7];
    const float* Wo    = (const float*)d_in[8];
    const float* bo    = (const float*)d_in[9];
    float* out = (float*)d_out;

    cudaFuncSetAttribute(k_fused, cudaFuncAttributeMaxDynamicSharedMemorySize, SMF);

    // order so k_fused is the 4th launch (profiled slot)
    k_combo<<<256, 256>>>(mask, Wo);
    k_prep<<<4096, 256>>>(msa, mask, gamma, beta, Wa, ba, Wb, bb);
    k_split_t<<<dim3(256, 4, 2), dim3(32, 8)>>>();
    k_fused<<<dim3(64, 64), 256, SMF>>>(bo, out);
}

// round 12
// speedup vs baseline: 1.3589x; 1.0742x over previous
#include <cuda_runtime.h>
#include <cuda_bf16.h>
#include <cstdint>

// Problem constants
#define SS_   128
#define NRES  256
#define DD    64
#define HH_   32
#define M_TOT 8192
#define KK2   1024

// ---------------- device scratch ----------------
__device__ __align__(16) float g_A[SS_ * M_TOT];
__device__ __align__(16) float g_B[SS_ * M_TOT];
__device__ __align__(16) __nv_bfloat16 g_Ah[M_TOT * SS_];
__device__ __align__(16) __nv_bfloat16 g_Al[M_TOT * SS_];
__device__ __align__(16) __nv_bfloat16 g_Bh[M_TOT * SS_];
__device__ __align__(16) __nv_bfloat16 g_Bl[M_TOT * SS_];
// Wo^T frag-linear per 16x16 tile (validated in R11)
__device__ __align__(16) __nv_bfloat16 g_Wph[64 * 4 * 256];
__device__ __align__(16) __nv_bfloat16 g_Wpl[64 * 4 * 256];
__device__ float g_invden[NRES];

__device__ __forceinline__ void split_bf16(float v, __nv_bfloat16& h, __nv_bfloat16& l) {
    h = __float2bfloat16(v);
    l = __float2bfloat16(v - __bfloat162float(h));
}
__device__ __forceinline__ uint32_t pack_bf2(float v0, float v1, float& l0, float& l1) {
    __nv_bfloat16 h0 = __float2bfloat16(v0), h1 = __float2bfloat16(v1);
    l0 = v0 - __bfloat162float(h0);
    l1 = v1 - __bfloat162float(h1);
    return (uint32_t)__bfloat16_as_ushort(h0) | ((uint32_t)__bfloat16_as_ushort(h1) << 16);
}
__device__ __forceinline__ uint32_t pack_bf2n(float v0, float v1) {
    __nv_bfloat16 h0 = __float2bfloat16(v0), h1 = __float2bfloat16(v1);
    return (uint32_t)__bfloat16_as_ushort(h0) | ((uint32_t)__bfloat16_as_ushort(h1) << 16);
}

__device__ __forceinline__ void cpa16(void* s, const void* g) {
    uint32_t sa = (uint32_t)__cvta_generic_to_shared(s);
    asm volatile("cp.async.cg.shared.global [%0], [%1], 16;" :: "r"(sa), "l"(g));
}
__device__ __forceinline__ void cpa_commit() {
    asm volatile("cp.async.commit_group;" ::: "memory");
}
template <int N>
__device__ __forceinline__ void cpa_wait() {
    asm volatile("cp.async.wait_group %0;" :: "n"(N) : "memory");
}

#define MMA16816(D, A0, A1, A2, A3, B0, B1) \
    asm volatile("mma.sync.aligned.m16n8k16.row.col.f32.bf16.bf16.f32 " \
        "{%0,%1,%2,%3}, {%4,%5,%6,%7}, {%8,%9}, {%0,%1,%2,%3};" \
        : "+f"((D)[0]), "+f"((D)[1]), "+f"((D)[2]), "+f"((D)[3]) \
        : "r"(A0), "r"(A1), "r"(A2), "r"(A3), "r"(B0), "r"(B1))

#define LDSM_X4(R0, R1, R2, R3, ADDR) \
    asm volatile("ldmatrix.sync.aligned.m8n8.x4.shared.b16 {%0,%1,%2,%3}, [%4];" \
        : "=r"(R0), "=r"(R1), "=r"(R2), "=r"(R3) : "r"(ADDR))

// ---------------- combo: Wo frag-linear pack + denom ----------------
__global__ void __launch_bounds__(256) k_combo(const float* __restrict__ mask,
                                               const float* __restrict__ Wo) {
    int idx = blockIdx.x * 256 + threadIdx.x;
    int tile = idx >> 8;
    int within = idx & 255;
    int lane = within >> 3, e = within & 7;
    int kt = tile >> 2, nf = tile & 3;
    int n = (lane >> 2) + ((e >> 2) << 3);
    int cc = lane & 3;
    int k = 2 * cc + (e & 1) + (((e >> 1) & 1) << 3);
    float v = Wo[(size_t)(kt * 16 + k) * 64 + nf * 16 + n];
    __nv_bfloat16 h, l; split_bf16(v, h, l);
    g_Wph[idx] = h;
    g_Wpl[idx] = l;

    if (blockIdx.x == 0) {
        int i = threadIdx.x;
        float s = 0.f;
        #pragma unroll 8
        for (int t = 0; t < SS_; ++t) s += mask[t * NRES + i];
        g_invden[i] = 1.0f / fmaxf(s, 1.0f);
    }
}

// ---------------- prep ----------------
__global__ void __launch_bounds__(256) k_prep(
    const float* __restrict__ x, const float* __restrict__ mask,
    const float* __restrict__ gamma, const float* __restrict__ beta,
    const float* __restrict__ Wa, const float* __restrict__ ba,
    const float* __restrict__ Wb, const float* __restrict__ bb)
{
    __shared__ float sx[8][64];
    int warp = threadIdx.x >> 5, lane = threadIdx.x & 31;
    int row = blockIdx.x * 8 + warp;
    const float* xr = x + (size_t)row * DD;

    float v0 = xr[lane], v1 = xr[lane + 32];
    float sum = v0 + v1;
    #pragma unroll
    for (int o = 16; o; o >>= 1) sum += __shfl_xor_sync(~0u, sum, o);
    float mu = sum * (1.0f / 64.0f);
    float d0 = v0 - mu, d1 = v1 - mu;
    float vs = d0 * d0 + d1 * d1;
    #pragma unroll
    for (int o = 16; o; o >>= 1) vs += __shfl_xor_sync(~0u, vs, o);
    float rstd = rsqrtf(vs * (1.0f / 64.0f) + 1e-5f);
    sx[warp][lane]      = d0 * rstd * gamma[lane]      + beta[lane];
    sx[warp][lane + 32] = d1 * rstd * gamma[lane + 32] + beta[lane + 32];
    __syncwarp();

    int s = row >> 8, i = row & 255;
    float m = mask[s * NRES + i];
    float a = ba[lane], b = bb[lane];
    #pragma unroll
    for (int d = 0; d < 64; ++d) {
        float xv = sx[warp][d];
        a = fmaf(xv, Wa[d * HH_ + lane], a);
        b = fmaf(xv, Wb[d * HH_ + lane], b);
    }
    a *= m * g_invden[i];
    b *= m;
    g_A[s * M_TOT + i * HH_ + lane] = a;
    g_B[s * M_TOT + i * HH_ + lane] = b;
}

// ---------------- transpose + split ----------------
__global__ void k_split_t() {
    __shared__ float t[32][33];
    const float* src = blockIdx.z ? g_B : g_A;
    __nv_bfloat16* oh = blockIdx.z ? g_Bh : g_Ah;
    __nv_bfloat16* ol = blockIdx.z ? g_Bl : g_Al;
    int tx = threadIdx.x, ty = threadIdx.y;
    #pragma unroll
    for (int k = 0; k < 4; ++k) {
        int s = blockIdx.y * 32 + ty + k * 8;
        int m = blockIdx.x * 32 + tx;
        t[ty + k * 8][tx] = src[(size_t)s * M_TOT + m];
    }
    __syncthreads();
    #pragma unroll
    for (int k = 0; k < 4; ++k) {
        int m = blockIdx.x * 32 + ty + k * 8;
        int s = blockIdx.y * 32 + tx;
        float v = t[tx][ty + k * 8];
        __nv_bfloat16 h, l; split_bf16(v, h, l);
        oh[(size_t)m * SS_ + s] = h;
        ol[(size_t)m * SS_ + s] = l;
    }
}

// ===================== FUSED kernel =====================
#define SKC 40
#define TILE_B (128 * SKC * 2)
#define STAGE_B (4 * TILE_B)
#define AE_LD 1032
#define SMF 98816

__global__ void __launch_bounds__(256, 2) k_fused(const float* __restrict__ bo,
                                                  float* __restrict__ out) {
    extern __shared__ char smc[];
    int tid = threadIdx.x;
    int wid = tid >> 5, lane = tid & 31;
    int wm = wid & 3, wn = wid >> 2;
    int bm = blockIdx.x, bn = blockIdx.y;
    int g = lane >> 2, cg = lane & 3;
    int lrow  = (lane & 7) + ((lane >> 3) & 1) * 8;
    int lcol8 = (lane >> 4) * 8;

    const __nv_bfloat16* gAh = g_Ah + (size_t)bm * 128 * SS_;
    const __nv_bfloat16* gAl = g_Al + (size_t)bm * 128 * SS_;
    const __nv_bfloat16* gBh = g_Bh + (size_t)bn * 128 * SS_;
    const __nv_bfloat16* gBl = g_Bl + (size_t)bn * 128 * SS_;

    // mainloop accumulators: d1[mt][nt][4], documented m16n8 layout
    float d1[2][8][4];
    #pragma unroll
    for (int a = 0; a < 2; ++a)
        #pragma unroll
        for (int b = 0; b < 8; ++b)
            #pragma unroll
            for (int e = 0; e < 4; ++e) d1[a][b][e] = 0.f;

    auto load_stage = [&](int stage, int ch) {
        char* base = smc + stage * STAGE_B;
        __nv_bfloat16* dAh = (__nv_bfloat16*)base;
        __nv_bfloat16* dAl = dAh + 128 * SKC;
        __nv_bfloat16* dBh = dAl + 128 * SKC;
        __nv_bfloat16* dBl = dBh + 128 * SKC;
        int kb = ch * 32;
        #pragma unroll
        for (int it = 0; it < 2; ++it) {
            int idx = it * 256 + tid;
            int row = idx >> 2, seg = idx & 3;
            size_t go = (size_t)row * SS_ + kb + seg * 8;
            int so = row * SKC + seg * 8;
            cpa16(dAh + so, gAh + go);
            cpa16(dAl + so, gAl + go);
            cpa16(dBh + so, gBh + go);
            cpa16(dBl + so, gBl + go);
        }
        cpa_commit();
    };

    // ---------------- Phase 1: pipelined mainloop (raw PTX mma) ----------------
    load_stage(0, 0);
    #pragma unroll
    for (int ch = 0; ch < 4; ++ch) {
        int cur = ch & 1;
        if (ch < 3) load_stage(cur ^ 1, ch + 1);
        if (ch < 3) cpa_wait<1>(); else cpa_wait<0>();
        __syncthreads();

        char* base = smc + cur * STAGE_B;
        __nv_bfloat16* sAh = (__nv_bfloat16*)base;
        __nv_bfloat16* sAl = sAh + 128 * SKC;
        __nv_bfloat16* sBh = sAl + 128 * SKC;
        __nv_bfloat16* sBl = sBh + 128 * SKC;

        #pragma unroll
        for (int ks = 0; ks < 2; ++ks) {
            int kc = ks * 16 + lcol8;
            // A frags: hi/lo for mf=0,1
            uint32_t ah[2][4], al[2][4];
            #pragma unroll
            for (int mf = 0; mf < 2; ++mf) {
                uint32_t adh = (uint32_t)__cvta_generic_to_shared(
                    sAh + (wm * 32 + mf * 16 + lrow) * SKC + kc);
                uint32_t adl = (uint32_t)__cvta_generic_to_shared(
                    sAl + (wm * 32 + mf * 16 + lrow) * SKC + kc);
                LDSM_X4(ah[mf][0], ah[mf][1], ah[mf][2], ah[mf][3], adh);
                LDSM_X4(al[mf][0], al[mf][1], al[mf][2], al[mf][3], adl);
            }
            // B frags (hi): 4 x4 calls cover 8 n-tiles
            uint32_t bb[8][2];
            int bnr = (wn * 64) + ((lane >> 4) & 1) * 8 + (lane & 7);
            int bkc = ks * 16 + ((lane >> 3) & 1) * 8;
            #pragma unroll
            for (int q = 0; q < 4; ++q) {
                uint32_t ad = (uint32_t)__cvta_generic_to_shared(
                    sBh + (bnr + q * 16) * SKC + bkc);
                LDSM_X4(bb[2*q][0], bb[2*q][1], bb[2*q+1][0], bb[2*q+1][1], ad);
            }
            #pragma unroll
            for (int nt = 0; nt < 8; ++nt) MMA16816(d1[0][nt], ah[0][0], ah[0][1], ah[0][2], ah[0][3], bb[nt][0], bb[nt][1]);
            #pragma unroll
            for (int nt = 0; nt < 8; ++nt) MMA16816(d1[1][nt], ah[1][0], ah[1][1], ah[1][2], ah[1][3], bb[nt][0], bb[nt][1]);
            #pragma unroll
            for (int nt = 0; nt < 8; ++nt) MMA16816(d1[0][nt], al[0][0], al[0][1], al[0][2], al[0][3], bb[nt][0], bb[nt][1]);
            #pragma unroll
            for (int nt = 0; nt < 8; ++nt) MMA16816(d1[1][nt], al[1][0], al[1][1], al[1][2], al[1][3], bb[nt][0], bb[nt][1]);
            // B frags (lo)
            #pragma unroll
            for (int q = 0; q < 4; ++q) {
                uint32_t ad = (uint32_t)__cvta_generic_to_shared(
                    sBl + (bnr + q * 16) * SKC + bkc);
                LDSM_X4(bb[2*q][0], bb[2*q][1], bb[2*q+1][0], bb[2*q+1][1], ad);
            }
            #pragma unroll
            for (int nt = 0; nt < 8; ++nt) MMA16816(d1[0][nt], ah[0][0], ah[0][1], ah[0][2], ah[0][3], bb[nt][0], bb[nt][1]);
            #pragma unroll
            for (int nt = 0; nt < 8; ++nt) MMA16816(d1[1][nt], ah[1][0], ah[1][1], ah[1][2], ah[1][3], bb[nt][0], bb[nt][1]);
        }
        __syncthreads();
    }

    // ---------------- Phase 2a: direct register conversion -> sAe hi/lo [16][1024] ----------------
    // thread (g,cg) holds d1[mf][nt]: rows m%32 = mf*16 + g (+8), cols n%32-part (nt&3)*8 + cg*2
    // sAe row r = wm*4 + wn*2 + (nt>>3? no) = wm*4 + wn*2 + (nt>>2); col c = (m%32)*32 + (nt&3)*8 + cg*2
    __nv_bfloat16* sAe_h = (__nv_bfloat16*)smc;
    __nv_bfloat16* sAe_l = sAe_h + 16 * AE_LD;
    float* sPart = (float*)(smc + 66048);
    {
        #pragma unroll
        for (int mf = 0; mf < 2; ++mf)
            #pragma unroll
            for (int nt = 0; nt < 8; ++nt) {
                int r = wm * 4 + wn * 2 + (nt >> 2);
                int cb = (nt & 3) * 8 + cg * 2;
                #pragma unroll
                for (int rh = 0; rh < 2; ++rh) {
                    float v0 = d1[mf][nt][rh * 2], v1 = d1[mf][nt][rh * 2 + 1];
                    float l0, l1;
                    uint32_t hp = pack_bf2(v0, v1, l0, l1);
                    uint32_t lp = pack_bf2n(l0, l1);
                    int c = (mf * 16 + g + rh * 8) * 32 + cb;
                    *(uint32_t*)(sAe_h + r * AE_LD + c) = hp;
                    *(uint32_t*)(sAe_l + r * AE_LD + c) = lp;
                }
            }
    }
    __syncthreads();

    // ---------------- Phase 2b: C16x64 = sAe @ Wo (double-buffered Wo regs) ----------------
    {
        float d[4][2][4];
        #pragma unroll
        for (int a = 0; a < 4; ++a)
            #pragma unroll
            for (int b = 0; b < 2; ++b)
                #pragma unroll
                for (int e = 0; e < 4; ++e) d[a][b][e] = 0.f;

        uint4 vh[2][4], vl[2][4];
        {
            int kt0 = wid * 8;
            #pragma unroll
            for (int nf = 0; nf < 4; ++nf) {
                vh[0][nf] = ((const uint4*)g_Wph)[(size_t)(kt0 * 4 + nf) * 32 + lane];
                vl[0][nf] = ((const uint4*)g_Wpl)[(size_t)(kt0 * 4 + nf) * 32 + lane];
            }
        }
        #pragma unroll
        for (int ks = 0; ks < 8; ++ks) {
            int cur = ks & 1;
            if (ks < 7) {
                int ktn = wid * 8 + ks + 1;
                #pragma unroll
                for (int nf = 0; nf < 4; ++nf) {
                    vh[cur ^ 1][nf] = ((const uint4*)g_Wph)[(size_t)(ktn * 4 + nf) * 32 + lane];
                    vl[cur ^ 1][nf] = ((const uint4*)g_Wpl)[(size_t)(ktn * 4 + nf) * 32 + lane];
                }
            }
            int kk = (wid * 8 + ks) * 16;
            uint32_t ah0, ah1, ah2, ah3, al0, al1, al2, al3;
            uint32_t adh = (uint32_t)__cvta_generic_to_shared(sAe_h + lrow * AE_LD + kk + lcol8);
            uint32_t adl = (uint32_t)__cvta_generic_to_shared(sAe_l + lrow * AE_LD + kk + lcol8);
            LDSM_X4(ah0, ah1, ah2, ah3, adh);
            LDSM_X4(al0, al1, al2, al3, adl);
            #pragma unroll
            for (int nf = 0; nf < 4; ++nf) {
                uint4 wh = vh[cur][nf], wl = vl[cur][nf];
                MMA16816(d[nf][0], ah0, ah1, ah2, ah3, wh.x, wh.y);
                MMA16816(d[nf][1], ah0, ah1, ah2, ah3, wh.z, wh.w);
                MMA16816(d[nf][0], al0, al1, al2, al3, wh.x, wh.y);
                MMA16816(d[nf][1], al0, al1, al2, al3, wh.z, wh.w);
                MMA16816(d[nf][0], ah0, ah1, ah2, ah3, wl.x, wl.y);
                MMA16816(d[nf][1], ah0, ah1, ah2, ah3, wl.z, wl.w);
            }
        }
        __syncthreads();

        #pragma unroll
        for (int nf = 0; nf < 4; ++nf)
            #pragma unroll
            for (int blk = 0; blk < 2; ++blk) {
                int col = nf * 16 + blk * 8 + cg * 2;
                float* p0 = sPart + wid * 1024 + g * 64 + col;
                p0[0] = d[nf][blk][0]; p0[1] = d[nf][blk][1];
                float* p1 = sPart + wid * 1024 + (g + 8) * 64 + col;
                p1[0] = d[nf][blk][2]; p1[1] = d[nf][blk][3];
            }
    }
    __syncthreads();

    // ---------------- Phase 2c: reduce 8 partials, +bo, store ----------------
    {
        int row = tid >> 4;
        int p4  = (tid & 15) * 4;
        float4 s = *(float4*)(sPart + row * 64 + p4);
        #pragma unroll
        for (int w = 1; w < 8; ++w) {
            float4 v = *(float4*)(sPart + w * 1024 + row * 64 + p4);
            s.x += v.x; s.y += v.y; s.z += v.z; s.w += v.w;
        }
        float4 bv = __ldg((const float4*)(bo + p4));
        s.x += bv.x; s.y += bv.y; s.z += bv.z; s.w += bv.w;
        size_t rg = (size_t)(bm * 4 + (row >> 2)) * 256 + bn * 4 + (row & 3);
        *(float4*)(out + rg * 64 + p4) = s;
    }
}

extern "C" void kernel_launch(void* const* d_in, const int* in_sizes, int n_in,
                              void* d_out, int out_size) {
    const float* msa   = (const float*)d_in[0];
    const float* mask  = (const float*)d_in[1];
    const float* gamma = (const float*)d_in[2];
    const float* beta  = (const float*)d_in[3];
    const float* Wa    = (const float*)d_in[4];
    const float* ba    = (const float*)d_in[5];
    const float* Wb    = (const float*)d_in[6];
    const float* bb    = (const float*)d_in[7];
    const float* Wo    = (const float*)d_in[8];
    const float* bo    = (const float*)d_in[9];
    float* out = (float*)d_out;

    cudaFuncSetAttribute(k_fused, cudaFuncAttributeMaxDynamicSharedMemorySize, SMF);

    k_combo<<<256, 256>>>(mask, Wo);
    k_prep<<<4096, 256>>>(msa, mask, gamma, beta, Wa, ba, Wb, bb);
    k_split_t<<<dim3(256, 4, 2), dim3(32, 8)>>>();
    k_fused<<<dim3(64, 64), 256, SMF>>>(bo, out);
}

// round 13
// speedup vs baseline: 1.3704x; 1.0084x over previous
#include <cuda_runtime.h>
#include <cuda_bf16.h>
#include <cstdint>

// Problem constants
#define SS_   128
#define NRES  256
#define DD    64
#define HH_   32
#define M_TOT 8192
#define KK2   1024

// ---------------- device scratch ----------------
__device__ __align__(16) __nv_bfloat16 g_Ah[M_TOT * SS_];
__device__ __align__(16) __nv_bfloat16 g_Al[M_TOT * SS_];
__device__ __align__(16) __nv_bfloat16 g_Bh[M_TOT * SS_];
__device__ __align__(16) __nv_bfloat16 g_Bl[M_TOT * SS_];
// Wo^T frag-linear per 16x16 tile (validated in R11)
__device__ __align__(16) __nv_bfloat16 g_Wph[64 * 4 * 256];
__device__ __align__(16) __nv_bfloat16 g_Wpl[64 * 4 * 256];

__device__ __forceinline__ void split_bf16(float v, __nv_bfloat16& h, __nv_bfloat16& l) {
    h = __float2bfloat16(v);
    l = __float2bfloat16(v - __bfloat162float(h));
}
__device__ __forceinline__ uint32_t pack_bf2(float v0, float v1, float& l0, float& l1) {
    __nv_bfloat16 h0 = __float2bfloat16(v0), h1 = __float2bfloat16(v1);
    l0 = v0 - __bfloat162float(h0);
    l1 = v1 - __bfloat162float(h1);
    return (uint32_t)__bfloat16_as_ushort(h0) | ((uint32_t)__bfloat16_as_ushort(h1) << 16);
}
__device__ __forceinline__ uint32_t pack_bf2n(float v0, float v1) {
    __nv_bfloat16 h0 = __float2bfloat16(v0), h1 = __float2bfloat16(v1);
    return (uint32_t)__bfloat16_as_ushort(h0) | ((uint32_t)__bfloat16_as_ushort(h1) << 16);
}

__device__ __forceinline__ void cpa16(void* s, const void* g) {
    uint32_t sa = (uint32_t)__cvta_generic_to_shared(s);
    asm volatile("cp.async.cg.shared.global [%0], [%1], 16;" :: "r"(sa), "l"(g));
}
__device__ __forceinline__ void cpa_commit() {
    asm volatile("cp.async.commit_group;" ::: "memory");
}
template <int N>
__device__ __forceinline__ void cpa_wait() {
    asm volatile("cp.async.wait_group %0;" :: "n"(N) : "memory");
}

#define MMA16816(D, A0, A1, A2, A3, B0, B1) \
    asm volatile("mma.sync.aligned.m16n8k16.row.col.f32.bf16.bf16.f32 " \
        "{%0,%1,%2,%3}, {%4,%5,%6,%7}, {%8,%9}, {%0,%1,%2,%3};" \
        : "+f"((D)[0]), "+f"((D)[1]), "+f"((D)[2]), "+f"((D)[3]) \
        : "r"(A0), "r"(A1), "r"(A2), "r"(A3), "r"(B0), "r"(B1))

#define LDSM_X4(R0, R1, R2, R3, ADDR) \
    asm volatile("ldmatrix.sync.aligned.m8n8.x4.shared.b16 {%0,%1,%2,%3}, [%4];" \
        : "=r"(R0), "=r"(R1), "=r"(R2), "=r"(R3) : "r"(ADDR))

// ---------------- combo: Wo frag-linear pack ----------------
__global__ void __launch_bounds__(256) k_combo(const float* __restrict__ Wo) {
    int idx = blockIdx.x * 256 + threadIdx.x;
    int tile = idx >> 8;
    int within = idx & 255;
    int lane = within >> 3, e = within & 7;
    int kt = tile >> 2, nf = tile & 3;
    int n = (lane >> 2) + ((e >> 2) << 3);
    int cc = lane & 3;
    int k = 2 * cc + (e & 1) + (((e >> 1) & 1) << 3);
    float v = Wo[(size_t)(kt * 16 + k) * 64 + nf * 16 + n];
    __nv_bfloat16 h, l; split_bf16(v, h, l);
    g_Wph[idx] = h;
    g_Wpl[idx] = l;
}

// ---------------- prep2: LN + proj + mask/denom + split + TRANSPOSED write ----------------
// One block per residue i. 8 warps; warp w handles rows s = w*16..w*16+15.
__global__ void __launch_bounds__(256) k_prep2(
    const float* __restrict__ x, const float* __restrict__ mask,
    const float* __restrict__ gamma, const float* __restrict__ beta,
    const float* __restrict__ Wa, const float* __restrict__ ba,
    const float* __restrict__ Wb, const float* __restrict__ bb)
{
    __shared__ float sx[8][64];
    __shared__ float sa[128][33];
    __shared__ float sb[128][33];
    __shared__ float smask[128];
    __shared__ float sinv;
    int i = blockIdx.x;
    int tid = threadIdx.x, warp = tid >> 5, lane = tid & 31;

    if (tid < 128) smask[tid] = mask[tid * NRES + i];
    __syncthreads();
    if (tid == 0) {
        float s = 0.f;
        #pragma unroll 8
        for (int t = 0; t < 128; ++t) s += smask[t];
        sinv = 1.0f / fmaxf(s, 1.0f);
    }
    __syncthreads();
    float inv = sinv;

    for (int r = 0; r < 16; ++r) {
        int s = warp * 16 + r;
        const float* xr = x + ((size_t)s * NRES + i) * DD;
        float v0 = xr[lane], v1 = xr[lane + 32];
        float sum = v0 + v1;
        #pragma unroll
        for (int o = 16; o; o >>= 1) sum += __shfl_xor_sync(~0u, sum, o);
        float mu = sum * (1.0f / 64.0f);
        float d0 = v0 - mu, d1 = v1 - mu;
        float vs = d0 * d0 + d1 * d1;
        #pragma unroll
        for (int o = 16; o; o >>= 1) vs += __shfl_xor_sync(~0u, vs, o);
        float rstd = rsqrtf(vs * (1.0f / 64.0f) + 1e-5f);
        sx[warp][lane]      = d0 * rstd * gamma[lane]      + beta[lane];
        sx[warp][lane + 32] = d1 * rstd * gamma[lane + 32] + beta[lane + 32];
        __syncwarp();

        float m = smask[s];
        float a = ba[lane], b = bb[lane];
        #pragma unroll
        for (int d = 0; d < 64; ++d) {
            float xv = sx[warp][d];
            a = fmaf(xv, Wa[d * HH_ + lane], a);
            b = fmaf(xv, Wb[d * HH_ + lane], b);
        }
        sa[s][lane] = a * m * inv;
        sb[s][lane] = b * m;
        __syncwarp();
    }
    __syncthreads();

    // transposed split write: thread -> (h = tid/8, s0 = (tid%8)*16), 16 s-values contiguous
    int h = tid >> 3, s0 = (tid & 7) * 16;
    size_t off = ((size_t)i * 32 + h) * SS_ + s0;
    {
        uint32_t hp[8], lp[8];
        #pragma unroll
        for (int j = 0; j < 8; ++j) {
            float u0 = sa[s0 + 2 * j][h], u1 = sa[s0 + 2 * j + 1][h];
            float l0, l1;
            hp[j] = pack_bf2(u0, u1, l0, l1);
            lp[j] = pack_bf2n(l0, l1);
        }
        *(uint4*)(g_Ah + off)     = make_uint4(hp[0], hp[1], hp[2], hp[3]);
        *(uint4*)(g_Ah + off + 8) = make_uint4(hp[4], hp[5], hp[6], hp[7]);
        *(uint4*)(g_Al + off)     = make_uint4(lp[0], lp[1], lp[2], lp[3]);
        *(uint4*)(g_Al + off + 8) = make_uint4(lp[4], lp[5], lp[6], lp[7]);
    }
    {
        uint32_t hp[8], lp[8];
        #pragma unroll
        for (int j = 0; j < 8; ++j) {
            float u0 = sb[s0 + 2 * j][h], u1 = sb[s0 + 2 * j + 1][h];
            float l0, l1;
            hp[j] = pack_bf2(u0, u1, l0, l1);
            lp[j] = pack_bf2n(l0, l1);
        }
        *(uint4*)(g_Bh + off)     = make_uint4(hp[0], hp[1], hp[2], hp[3]);
        *(uint4*)(g_Bh + off + 8) = make_uint4(hp[4], hp[5], hp[6], hp[7]);
        *(uint4*)(g_Bl + off)     = make_uint4(lp[0], lp[1], lp[2], lp[3]);
        *(uint4*)(g_Bl + off + 8) = make_uint4(lp[4], lp[5], lp[6], lp[7]);
    }
}

// ===================== FUSED kernel =====================
#define SKC 40
#define TILE_B (128 * SKC * 2)
#define STAGE_B (4 * TILE_B)
#define AE_LD 1032
#define SMF 98816

__global__ void __launch_bounds__(256, 2) k_fused(const float* __restrict__ bo,
                                                  float* __restrict__ out) {
    extern __shared__ char smc[];
    int tid = threadIdx.x;
    int wid = tid >> 5, lane = tid & 31;
    int wm = wid & 3, wn = wid >> 2;
    int bm = blockIdx.x, bn = blockIdx.y;
    int g = lane >> 2, cg = lane & 3;
    int lrow  = (lane & 7) + ((lane >> 3) & 1) * 8;
    int lcol8 = (lane >> 4) * 8;

    const __nv_bfloat16* gAh = g_Ah + (size_t)bm * 128 * SS_;
    const __nv_bfloat16* gAl = g_Al + (size_t)bm * 128 * SS_;
    const __nv_bfloat16* gBh = g_Bh + (size_t)bn * 128 * SS_;
    const __nv_bfloat16* gBl = g_Bl + (size_t)bn * 128 * SS_;

    float d1[2][8][4];
    #pragma unroll
    for (int a = 0; a < 2; ++a)
        #pragma unroll
        for (int b = 0; b < 8; ++b)
            #pragma unroll
            for (int e = 0; e < 4; ++e) d1[a][b][e] = 0.f;

    auto load_stage = [&](int stage, int ch) {
        char* base = smc + stage * STAGE_B;
        __nv_bfloat16* dAh = (__nv_bfloat16*)base;
        __nv_bfloat16* dAl = dAh + 128 * SKC;
        __nv_bfloat16* dBh = dAl + 128 * SKC;
        __nv_bfloat16* dBl = dBh + 128 * SKC;
        int kb = ch * 32;
        #pragma unroll
        for (int it = 0; it < 2; ++it) {
            int idx = it * 256 + tid;
            int row = idx >> 2, seg = idx & 3;
            size_t go = (size_t)row * SS_ + kb + seg * 8;
            int so = row * SKC + seg * 8;
            cpa16(dAh + so, gAh + go);
            cpa16(dAl + so, gAl + go);
            cpa16(dBh + so, gBh + go);
            cpa16(dBl + so, gBl + go);
        }
        cpa_commit();
    };

    // ---------------- Phase 1: pipelined mainloop (raw PTX mma) ----------------
    load_stage(0, 0);
    #pragma unroll
    for (int ch = 0; ch < 4; ++ch) {
        int cur = ch & 1;
        if (ch < 3) load_stage(cur ^ 1, ch + 1);
        if (ch < 3) cpa_wait<1>(); else cpa_wait<0>();
        __syncthreads();

        char* base = smc + cur * STAGE_B;
        __nv_bfloat16* sAh = (__nv_bfloat16*)base;
        __nv_bfloat16* sAl = sAh + 128 * SKC;
        __nv_bfloat16* sBh = sAl + 128 * SKC;
        __nv_bfloat16* sBl = sBh + 128 * SKC;

        #pragma unroll
        for (int ks = 0; ks < 2; ++ks) {
            int kc = ks * 16 + lcol8;
            uint32_t ah[2][4], al[2][4];
            #pragma unroll
            for (int mf = 0; mf < 2; ++mf) {
                uint32_t adh = (uint32_t)__cvta_generic_to_shared(
                    sAh + (wm * 32 + mf * 16 + lrow) * SKC + kc);
                uint32_t adl = (uint32_t)__cvta_generic_to_shared(
                    sAl + (wm * 32 + mf * 16 + lrow) * SKC + kc);
                LDSM_X4(ah[mf][0], ah[mf][1], ah[mf][2], ah[mf][3], adh);
                LDSM_X4(al[mf][0], al[mf][1], al[mf][2], al[mf][3], adl);
            }
            uint32_t bb[8][2];
            int bnr = (wn * 64) + ((lane >> 4) & 1) * 8 + (lane & 7);
            int bkc = ks * 16 + ((lane >> 3) & 1) * 8;
            #pragma unroll
            for (int q = 0; q < 4; ++q) {
                uint32_t ad = (uint32_t)__cvta_generic_to_shared(
                    sBh + (bnr + q * 16) * SKC + bkc);
                LDSM_X4(bb[2*q][0], bb[2*q][1], bb[2*q+1][0], bb[2*q+1][1], ad);
            }
            #pragma unroll
            for (int nt = 0; nt < 8; ++nt) MMA16816(d1[0][nt], ah[0][0], ah[0][1], ah[0][2], ah[0][3], bb[nt][0], bb[nt][1]);
            #pragma unroll
            for (int nt = 0; nt < 8; ++nt) MMA16816(d1[1][nt], ah[1][0], ah[1][1], ah[1][2], ah[1][3], bb[nt][0], bb[nt][1]);
            #pragma unroll
            for (int nt = 0; nt < 8; ++nt) MMA16816(d1[0][nt], al[0][0], al[0][1], al[0][2], al[0][3], bb[nt][0], bb[nt][1]);
            #pragma unroll
            for (int nt = 0; nt < 8; ++nt) MMA16816(d1[1][nt], al[1][0], al[1][1], al[1][2], al[1][3], bb[nt][0], bb[nt][1]);
            #pragma unroll
            for (int q = 0; q < 4; ++q) {
                uint32_t ad = (uint32_t)__cvta_generic_to_shared(
                    sBl + (bnr + q * 16) * SKC + bkc);
                LDSM_X4(bb[2*q][0], bb[2*q][1], bb[2*q+1][0], bb[2*q+1][1], ad);
            }
            #pragma unroll
            for (int nt = 0; nt < 8; ++nt) MMA16816(d1[0][nt], ah[0][0], ah[0][1], ah[0][2], ah[0][3], bb[nt][0], bb[nt][1]);
            #pragma unroll
            for (int nt = 0; nt < 8; ++nt) MMA16816(d1[1][nt], ah[1][0], ah[1][1], ah[1][2], ah[1][3], bb[nt][0], bb[nt][1]);
        }
        __syncthreads();
    }

    // ---------------- Phase 2: epilogue ----------------
    __nv_bfloat16* sAe_h = (__nv_bfloat16*)smc;
    __nv_bfloat16* sAe_l = sAe_h + 16 * AE_LD;
    float* sPart = (float*)(smc + 66048);

    // prefetch Wo ks=0 regs BEFORE the conversion (hide LDG latency behind 2a)
    uint4 vh[2][4], vl[2][4];
    {
        int kt0 = wid * 8;
        #pragma unroll
        for (int nf = 0; nf < 4; ++nf) {
            vh[0][nf] = ((const uint4*)g_Wph)[(size_t)(kt0 * 4 + nf) * 32 + lane];
            vl[0][nf] = ((const uint4*)g_Wpl)[(size_t)(kt0 * 4 + nf) * 32 + lane];
        }
    }

    // Phase 2a: direct register conversion -> sAe hi/lo [16][1024]
    {
        #pragma unroll
        for (int mf = 0; mf < 2; ++mf)
            #pragma unroll
            for (int nt = 0; nt < 8; ++nt) {
                int r = wm * 4 + wn * 2 + (nt >> 2);
                int cb = (nt & 3) * 8 + cg * 2;
                #pragma unroll
                for (int rh = 0; rh < 2; ++rh) {
                    float v0 = d1[mf][nt][rh * 2], v1 = d1[mf][nt][rh * 2 + 1];
                    float l0, l1;
                    uint32_t hp = pack_bf2(v0, v1, l0, l1);
                    uint32_t lp = pack_bf2n(l0, l1);
                    int c = (mf * 16 + g + rh * 8) * 32 + cb;
                    *(uint32_t*)(sAe_h + r * AE_LD + c) = hp;
                    *(uint32_t*)(sAe_l + r * AE_LD + c) = lp;
                }
            }
    }
    __syncthreads();

    // Phase 2b: C16x64 = sAe @ Wo (double-buffered Wo regs)
    {
        float d[4][2][4];
        #pragma unroll
        for (int a = 0; a < 4; ++a)
            #pragma unroll
            for (int b = 0; b < 2; ++b)
                #pragma unroll
                for (int e = 0; e < 4; ++e) d[a][b][e] = 0.f;

        #pragma unroll
        for (int ks = 0; ks < 8; ++ks) {
            int cur = ks & 1;
            if (ks < 7) {
                int ktn = wid * 8 + ks + 1;
                #pragma unroll
                for (int nf = 0; nf < 4; ++nf) {
                    vh[cur ^ 1][nf] = ((const uint4*)g_Wph)[(size_t)(ktn * 4 + nf) * 32 + lane];
                    vl[cur ^ 1][nf] = ((const uint4*)g_Wpl)[(size_t)(ktn * 4 + nf) * 32 + lane];
                }
            }
            int kk = (wid * 8 + ks) * 16;
            uint32_t ah0, ah1, ah2, ah3, al0, al1, al2, al3;
            uint32_t adh = (uint32_t)__cvta_generic_to_shared(sAe_h + lrow * AE_LD + kk + lcol8);
            uint32_t adl = (uint32_t)__cvta_generic_to_shared(sAe_l + lrow * AE_LD + kk + lcol8);
            LDSM_X4(ah0, ah1, ah2, ah3, adh);
            LDSM_X4(al0, al1, al2, al3, adl);
            #pragma unroll
            for (int nf = 0; nf < 4; ++nf) {
                uint4 wh = vh[cur][nf], wl = vl[cur][nf];
                MMA16816(d[nf][0], ah0, ah1, ah2, ah3, wh.x, wh.y);
                MMA16816(d[nf][1], ah0, ah1, ah2, ah3, wh.z, wh.w);
                MMA16816(d[nf][0], al0, al1, al2, al3, wh.x, wh.y);
                MMA16816(d[nf][1], al0, al1, al2, al3, wh.z, wh.w);
                MMA16816(d[nf][0], ah0, ah1, ah2, ah3, wl.x, wl.y);
                MMA16816(d[nf][1], ah0, ah1, ah2, ah3, wl.z, wl.w);
            }
        }
        __syncthreads();

        #pragma unroll
        for (int nf = 0; nf < 4; ++nf)
            #pragma unroll
            for (int blk = 0; blk < 2; ++blk) {
                int col = nf * 16 + blk * 8 + cg * 2;
                float* p0 = sPart + wid * 1024 + g * 64 + col;
                p0[0] = d[nf][blk][0]; p0[1] = d[nf][blk][1];
                float* p1 = sPart + wid * 1024 + (g + 8) * 64 + col;
                p1[0] = d[nf][blk][2]; p1[1] = d[nf][blk][3];
            }
    }
    __syncthreads();

    // Phase 2c: reduce 8 partials, +bo, store
    {
        int row = tid >> 4;
        int p4  = (tid & 15) * 4;
        float4 s = *(float4*)(sPart + row * 64 + p4);
        #pragma unroll
        for (int w = 1; w < 8; ++w) {
            float4 v = *(float4*)(sPart + w * 1024 + row * 64 + p4);
            s.x += v.x; s.y += v.y; s.z += v.z; s.w += v.w;
        }
        float4 bv = __ldg((const float4*)(bo + p4));
        s.x += bv.x; s.y += bv.y; s.z += bv.z; s.w += bv.w;
        size_t rg = (size_t)(bm * 4 + (row >> 2)) * 256 + bn * 4 + (row & 3);
        *(float4*)(out + rg * 64 + p4) = s;
    }
}

extern "C" void kernel_launch(void* const* d_in, const int* in_sizes, int n_in,
                              void* d_out, int out_size) {
    const float* msa   = (const float*)d_in[0];
    const float* mask  = (const float*)d_in[1];
    const float* gamma = (const float*)d_in[2];
    const float* beta  = (const float*)d_in[3];
    const float* Wa    = (const float*)d_in[4];
    const float* ba    = (const float*)d_in[5];
    const float* Wb    = (const float*)d_in[6];
    const float* bb    = (const float*)d_in[7];
    const float* Wo    = (const float*)d_in[8];
    const float* bo    = (const float*)d_in[9];
    float* out = (float*)d_out;

    cudaFuncSetAttribute(k_fused, cudaFuncAttributeMaxDynamicSharedMemorySize, SMF);

    k_combo<<<256, 256>>>(Wo);
    k_prep2<<<256, 256>>>(msa, mask, gamma, beta, Wa, ba, Wb, bb);
    k_fused<<<dim3(64, 64), 256, SMF>>>(bo, out);
}

// round 14
// speedup vs baseline: 1.3835x; 1.0096x over previous
#include <cuda_runtime.h>
#include <cuda_bf16.h>
#include <cstdint>

// Problem constants
#define SS_   128
#define NRES  256
#define DD    64
#define HH_   32
#define M_TOT 8192
#define KK2   1024

// ---------------- device scratch ----------------
__device__ __align__(16) __nv_bfloat16 g_Ah[M_TOT * SS_];
__device__ __align__(16) __nv_bfloat16 g_Al[M_TOT * SS_];
__device__ __align__(16) __nv_bfloat16 g_Bh[M_TOT * SS_];
__device__ __align__(16) __nv_bfloat16 g_Bl[M_TOT * SS_];
// Wo^T frag-linear per 16x16 tile (validated in R11)
__device__ __align__(16) __nv_bfloat16 g_Wph[64 * 4 * 256];
__device__ __align__(16) __nv_bfloat16 g_Wpl[64 * 4 * 256];

__device__ __forceinline__ void split_bf16(float v, __nv_bfloat16& h, __nv_bfloat16& l) {
    h = __float2bfloat16(v);
    l = __float2bfloat16(v - __bfloat162float(h));
}
__device__ __forceinline__ uint32_t pack_bf2(float v0, float v1, float& l0, float& l1) {
    __nv_bfloat16 h0 = __float2bfloat16(v0), h1 = __float2bfloat16(v1);
    l0 = v0 - __bfloat162float(h0);
    l1 = v1 - __bfloat162float(h1);
    return (uint32_t)__bfloat16_as_ushort(h0) | ((uint32_t)__bfloat16_as_ushort(h1) << 16);
}
__device__ __forceinline__ uint32_t pack_bf2n(float v0, float v1) {
    __nv_bfloat16 h0 = __float2bfloat16(v0), h1 = __float2bfloat16(v1);
    return (uint32_t)__bfloat16_as_ushort(h0) | ((uint32_t)__bfloat16_as_ushort(h1) << 16);
}

__device__ __forceinline__ void cpa16(void* s, const void* g) {
    uint32_t sa = (uint32_t)__cvta_generic_to_shared(s);
    asm volatile("cp.async.cg.shared.global [%0], [%1], 16;" :: "r"(sa), "l"(g));
}
__device__ __forceinline__ void cpa_commit() {
    asm volatile("cp.async.commit_group;" ::: "memory");
}
template <int N>
__device__ __forceinline__ void cpa_wait() {
    asm volatile("cp.async.wait_group %0;" :: "n"(N) : "memory");
}

#define MMA16816(D, A0, A1, A2, A3, B0, B1) \
    asm volatile("mma.sync.aligned.m16n8k16.row.col.f32.bf16.bf16.f32 " \
        "{%0,%1,%2,%3}, {%4,%5,%6,%7}, {%8,%9}, {%0,%1,%2,%3};" \
        : "+f"((D)[0]), "+f"((D)[1]), "+f"((D)[2]), "+f"((D)[3]) \
        : "r"(A0), "r"(A1), "r"(A2), "r"(A3), "r"(B0), "r"(B1))

#define LDSM_X4(R0, R1, R2, R3, ADDR) \
    asm volatile("ldmatrix.sync.aligned.m8n8.x4.shared.b16 {%0,%1,%2,%3}, [%4];" \
        : "=r"(R0), "=r"(R1), "=r"(R2), "=r"(R3) : "r"(ADDR))

// ---------------- k_pre: prep (blocks 0-1023) + Wo pack (blocks 1024-1279) ----------------
// prep block b: i = b>>2, sg = b&3 -> handles s in [sg*32, sg*32+32).
// 8 warps, each warp 4 s-rows. invden computed in-block from the full mask column.
__global__ void __launch_bounds__(256) k_pre(
    const float* __restrict__ x, const float* __restrict__ mask,
    const float* __restrict__ gamma, const float* __restrict__ beta,
    const float* __restrict__ Wa, const float* __restrict__ ba,
    const float* __restrict__ Wb, const float* __restrict__ bb,
    const float* __restrict__ Wo)
{
    int b = blockIdx.x;
    int tid = threadIdx.x;

    if (b >= 1024) {
        // ---- Wo frag-linear pack ----
        int idx = (b - 1024) * 256 + tid;
        int tile = idx >> 8;
        int within = idx & 255;
        int lane = within >> 3, e = within & 7;
        int kt = tile >> 2, nf = tile & 3;
        int n = (lane >> 2) + ((e >> 2) << 3);
        int cc = lane & 3;
        int k = 2 * cc + (e & 1) + (((e >> 1) & 1) << 3);
        float v = Wo[(size_t)(kt * 16 + k) * 64 + nf * 16 + n];
        __nv_bfloat16 h, l; split_bf16(v, h, l);
        g_Wph[idx] = h;
        g_Wpl[idx] = l;
        return;
    }

    // ---- prep ----
    __shared__ float sx[8][64];
    __shared__ float sa[32][33];
    __shared__ float sb[32][33];
    __shared__ float smask[128];
    __shared__ float sinv;
    int i = b >> 2, sg = b & 3;
    int warp = tid >> 5, lane = tid & 31;

    if (tid < 128) smask[tid] = mask[tid * NRES + i];
    __syncthreads();
    if (tid == 0) {
        float s = 0.f;
        #pragma unroll 8
        for (int t = 0; t < 128; ++t) s += smask[t];
        sinv = 1.0f / fmaxf(s, 1.0f);
    }
    __syncthreads();
    float inv = sinv;

    #pragma unroll
    for (int r = 0; r < 4; ++r) {
        int sl = warp * 4 + r;            // 0..31
        int s = sg * 32 + sl;
        const float* xr = x + ((size_t)s * NRES + i) * DD;
        float v0 = xr[lane], v1 = xr[lane + 32];
        float sum = v0 + v1;
        #pragma unroll
        for (int o = 16; o; o >>= 1) sum += __shfl_xor_sync(~0u, sum, o);
        float mu = sum * (1.0f / 64.0f);
        float d0 = v0 - mu, d1 = v1 - mu;
        float vs = d0 * d0 + d1 * d1;
        #pragma unroll
        for (int o = 16; o; o >>= 1) vs += __shfl_xor_sync(~0u, vs, o);
        float rstd = rsqrtf(vs * (1.0f / 64.0f) + 1e-5f);
        sx[warp][lane]      = d0 * rstd * gamma[lane]      + beta[lane];
        sx[warp][lane + 32] = d1 * rstd * gamma[lane + 32] + beta[lane + 32];
        __syncwarp();

        float m = smask[s];
        float a = ba[lane], bv = bb[lane];
        #pragma unroll
        for (int d = 0; d < 64; ++d) {
            float xv = sx[warp][d];
            a  = fmaf(xv, Wa[d * HH_ + lane], a);
            bv = fmaf(xv, Wb[d * HH_ + lane], bv);
        }
        sa[sl][lane] = a * m * inv;
        sb[sl][lane] = bv * m;
        __syncwarp();
    }
    __syncthreads();

    // transposed split write: thread -> h = tid/8 (0..31), j = tid%8 -> 4 consecutive s
    int h = tid >> 3, j = tid & 7;
    size_t off = ((size_t)i * 32 + h) * SS_ + sg * 32 + j * 4;
    {
        float l0, l1, l2, l3;
        uint32_t h0 = pack_bf2(sa[j * 4 + 0][h], sa[j * 4 + 1][h], l0, l1);
        uint32_t h1 = pack_bf2(sa[j * 4 + 2][h], sa[j * 4 + 3][h], l2, l3);
        *(uint2*)(g_Ah + off) = make_uint2(h0, h1);
        *(uint2*)(g_Al + off) = make_uint2(pack_bf2n(l0, l1), pack_bf2n(l2, l3));
    }
    {
        float l0, l1, l2, l3;
        uint32_t h0 = pack_bf2(sb[j * 4 + 0][h], sb[j * 4 + 1][h], l0, l1);
        uint32_t h1 = pack_bf2(sb[j * 4 + 2][h], sb[j * 4 + 3][h], l2, l3);
        *(uint2*)(g_Bh + off) = make_uint2(h0, h1);
        *(uint2*)(g_Bl + off) = make_uint2(pack_bf2n(l0, l1), pack_bf2n(l2, l3));
    }
}

// ===================== FUSED kernel (unchanged from R12/R13) =====================
#define SKC 40
#define TILE_B (128 * SKC * 2)
#define STAGE_B (4 * TILE_B)
#define AE_LD 1032
#define SMF 98816

__global__ void __launch_bounds__(256, 2) k_fused(const float* __restrict__ bo,
                                                  float* __restrict__ out) {
    extern __shared__ char smc[];
    int tid = threadIdx.x;
    int wid = tid >> 5, lane = tid & 31;
    int wm = wid & 3, wn = wid >> 2;
    int bm = blockIdx.x, bn = blockIdx.y;
    int g = lane >> 2, cg = lane & 3;
    int lrow  = (lane & 7) + ((lane >> 3) & 1) * 8;
    int lcol8 = (lane >> 4) * 8;

    const __nv_bfloat16* gAh = g_Ah + (size_t)bm * 128 * SS_;
    const __nv_bfloat16* gAl = g_Al + (size_t)bm * 128 * SS_;
    const __nv_bfloat16* gBh = g_Bh + (size_t)bn * 128 * SS_;
    const __nv_bfloat16* gBl = g_Bl + (size_t)bn * 128 * SS_;

    float d1[2][8][4];
    #pragma unroll
    for (int a = 0; a < 2; ++a)
        #pragma unroll
        for (int b = 0; b < 8; ++b)
            #pragma unroll
            for (int e = 0; e < 4; ++e) d1[a][b][e] = 0.f;

    auto load_stage = [&](int stage, int ch) {
        char* base = smc + stage * STAGE_B;
        __nv_bfloat16* dAh = (__nv_bfloat16*)base;
        __nv_bfloat16* dAl = dAh + 128 * SKC;
        __nv_bfloat16* dBh = dAl + 128 * SKC;
        __nv_bfloat16* dBl = dBh + 128 * SKC;
        int kb = ch * 32;
        #pragma unroll
        for (int it = 0; it < 2; ++it) {
            int idx = it * 256 + tid;
            int row = idx >> 2, seg = idx & 3;
            size_t go = (size_t)row * SS_ + kb + seg * 8;
            int so = row * SKC + seg * 8;
            cpa16(dAh + so, gAh + go);
            cpa16(dAl + so, gAl + go);
            cpa16(dBh + so, gBh + go);
            cpa16(dBl + so, gBl + go);
        }
        cpa_commit();
    };

    load_stage(0, 0);
    #pragma unroll
    for (int ch = 0; ch < 4; ++ch) {
        int cur = ch & 1;
        if (ch < 3) load_stage(cur ^ 1, ch + 1);
        if (ch < 3) cpa_wait<1>(); else cpa_wait<0>();
        __syncthreads();

        char* base = smc + cur * STAGE_B;
        __nv_bfloat16* sAh = (__nv_bfloat16*)base;
        __nv_bfloat16* sAl = sAh + 128 * SKC;
        __nv_bfloat16* sBh = sAl + 128 * SKC;
        __nv_bfloat16* sBl = sBh + 128 * SKC;

        #pragma unroll
        for (int ks = 0; ks < 2; ++ks) {
            int kc = ks * 16 + lcol8;
            uint32_t ah[2][4], al[2][4];
            #pragma unroll
            for (int mf = 0; mf < 2; ++mf) {
                uint32_t adh = (uint32_t)__cvta_generic_to_shared(
                    sAh + (wm * 32 + mf * 16 + lrow) * SKC + kc);
                uint32_t adl = (uint32_t)__cvta_generic_to_shared(
                    sAl + (wm * 32 + mf * 16 + lrow) * SKC + kc);
                LDSM_X4(ah[mf][0], ah[mf][1], ah[mf][2], ah[mf][3], adh);
                LDSM_X4(al[mf][0], al[mf][1], al[mf][2], al[mf][3], adl);
            }
            uint32_t bb[8][2];
            int bnr = (wn * 64) + ((lane >> 4) & 1) * 8 + (lane & 7);
            int bkc = ks * 16 + ((lane >> 3) & 1) * 8;
            #pragma unroll
            for (int q = 0; q < 4; ++q) {
                uint32_t ad = (uint32_t)__cvta_generic_to_shared(
                    sBh + (bnr + q * 16) * SKC + bkc);
                LDSM_X4(bb[2*q][0], bb[2*q][1], bb[2*q+1][0], bb[2*q+1][1], ad);
            }
            #pragma unroll
            for (int nt = 0; nt < 8; ++nt) MMA16816(d1[0][nt], ah[0][0], ah[0][1], ah[0][2], ah[0][3], bb[nt][0], bb[nt][1]);
            #pragma unroll
            for (int nt = 0; nt < 8; ++nt) MMA16816(d1[1][nt], ah[1][0], ah[1][1], ah[1][2], ah[1][3], bb[nt][0], bb[nt][1]);
            #pragma unroll
            for (int nt = 0; nt < 8; ++nt) MMA16816(d1[0][nt], al[0][0], al[0][1], al[0][2], al[0][3], bb[nt][0], bb[nt][1]);
            #pragma unroll
            for (int nt = 0; nt < 8; ++nt) MMA16816(d1[1][nt], al[1][0], al[1][1], al[1][2], al[1][3], bb[nt][0], bb[nt][1]);
            #pragma unroll
            for (int q = 0; q < 4; ++q) {
                uint32_t ad = (uint32_t)__cvta_generic_to_shared(
                    sBl + (bnr + q * 16) * SKC + bkc);
                LDSM_X4(bb[2*q][0], bb[2*q][1], bb[2*q+1][0], bb[2*q+1][1], ad);
            }
            #pragma unroll
            for (int nt = 0; nt < 8; ++nt) MMA16816(d1[0][nt], ah[0][0], ah[0][1], ah[0][2], ah[0][3], bb[nt][0], bb[nt][1]);
            #pragma unroll
            for (int nt = 0; nt < 8; ++nt) MMA16816(d1[1][nt], ah[1][0], ah[1][1], ah[1][2], ah[1][3], bb[nt][0], bb[nt][1]);
        }
        __syncthreads();
    }

    // ---------------- Phase 2: epilogue ----------------
    __nv_bfloat16* sAe_h = (__nv_bfloat16*)smc;
    __nv_bfloat16* sAe_l = sAe_h + 16 * AE_LD;
    float* sPart = (float*)(smc + 66048);

    uint4 vh[2][4], vl[2][4];
    {
        int kt0 = wid * 8;
        #pragma unroll
        for (int nf = 0; nf < 4; ++nf) {
            vh[0][nf] = ((const uint4*)g_Wph)[(size_t)(kt0 * 4 + nf) * 32 + lane];
            vl[0][nf] = ((const uint4*)g_Wpl)[(size_t)(kt0 * 4 + nf) * 32 + lane];
        }
    }

    {
        #pragma unroll
        for (int mf = 0; mf < 2; ++mf)
            #pragma unroll
            for (int nt = 0; nt < 8; ++nt) {
                int r = wm * 4 + wn * 2 + (nt >> 2);
                int cb = (nt & 3) * 8 + cg * 2;
                #pragma unroll
                for (int rh = 0; rh < 2; ++rh) {
                    float v0 = d1[mf][nt][rh * 2], v1 = d1[mf][nt][rh * 2 + 1];
                    float l0, l1;
                    uint32_t hp = pack_bf2(v0, v1, l0, l1);
                    uint32_t lp = pack_bf2n(l0, l1);
                    int c = (mf * 16 + g + rh * 8) * 32 + cb;
                    *(uint32_t*)(sAe_h + r * AE_LD + c) = hp;
                    *(uint32_t*)(sAe_l + r * AE_LD + c) = lp;
                }
            }
    }
    __syncthreads();

    {
        float d[4][2][4];
        #pragma unroll
        for (int a = 0; a < 4; ++a)
            #pragma unroll
            for (int b = 0; b < 2; ++b)
                #pragma unroll
                for (int e = 0; e < 4; ++e) d[a][b][e] = 0.f;

        #pragma unroll
        for (int ks = 0; ks < 8; ++ks) {
            int cur = ks & 1;
            if (ks < 7) {
                int ktn = wid * 8 + ks + 1;
                #pragma unroll
                for (int nf = 0; nf < 4; ++nf) {
                    vh[cur ^ 1][nf] = ((const uint4*)g_Wph)[(size_t)(ktn * 4 + nf) * 32 + lane];
                    vl[cur ^ 1][nf] = ((const uint4*)g_Wpl)[(size_t)(ktn * 4 + nf) * 32 + lane];
                }
            }
            int kk = (wid * 8 + ks) * 16;
            uint32_t ah0, ah1, ah2, ah3, al0, al1, al2, al3;
            uint32_t adh = (uint32_t)__cvta_generic_to_shared(sAe_h + lrow * AE_LD + kk + lcol8);
            uint32_t adl = (uint32_t)__cvta_generic_to_shared(sAe_l + lrow * AE_LD + kk + lcol8);
            LDSM_X4(ah0, ah1, ah2, ah3, adh);
            LDSM_X4(al0, al1, al2, al3, adl);
            #pragma unroll
            for (int nf = 0; nf < 4; ++nf) {
                uint4 wh = vh[cur][nf], wl = vl[cur][nf];
                MMA16816(d[nf][0], ah0, ah1, ah2, ah3, wh.x, wh.y);
                MMA16816(d[nf][1], ah0, ah1, ah2, ah3, wh.z, wh.w);
                MMA16816(d[nf][0], al0, al1, al2, al3, wh.x, wh.y);
                MMA16816(d[nf][1], al0, al1, al2, al3, wh.z, wh.w);
                MMA16816(d[nf][0], ah0, ah1, ah2, ah3, wl.x, wl.y);
                MMA16816(d[nf][1], ah0, ah1, ah2, ah3, wl.z, wl.w);
            }
        }
        __syncthreads();

        #pragma unroll
        for (int nf = 0; nf < 4; ++nf)
            #pragma unroll
            for (int blk = 0; blk < 2; ++blk) {
                int col = nf * 16 + blk * 8 + cg * 2;
                float* p0 = sPart + wid * 1024 + g * 64 + col;
                p0[0] = d[nf][blk][0]; p0[1] = d[nf][blk][1];
                float* p1 = sPart + wid * 1024 + (g + 8) * 64 + col;
                p1[0] = d[nf][blk][2]; p1[1] = d[nf][blk][3];
            }
    }
    __syncthreads();

    {
        int row = tid >> 4;
        int p4  = (tid & 15) * 4;
        float4 s = *(float4*)(sPart + row * 64 + p4);
        #pragma unroll
        for (int w = 1; w < 8; ++w) {
            float4 v = *(float4*)(sPart + w * 1024 + row * 64 + p4);
            s.x += v.x; s.y += v.y; s.z += v.z; s.w += v.w;
        }
        float4 bv = __ldg((const float4*)(bo + p4));
        s.x += bv.x; s.y += bv.y; s.z += bv.z; s.w += bv.w;
        size_t rg = (size_t)(bm * 4 + (row >> 2)) * 256 + bn * 4 + (row & 3);
        *(float4*)(out + rg * 64 + p4) = s;
    }
}

extern "C" void kernel_launch(void* const* d_in, const int* in_sizes, int n_in,
                              void* d_out, int out_size) {
    const float* msa   = (const float*)d_in[0];
    const float* mask  = (const float*)d_in[1];
    const float* gamma = (const float*)d_in[2];
    const float* beta  = (const float*)d_in[3];
    const float* Wa    = (const float*)d_in[4];
    const float* ba    = (const float*)d_in[5];
    const float* Wb    = (const float*)d_in[6];
    const float* bb    = (const float*)d_in[7];
    const float* Wo    = (const float*)d_in[8];
    const float* bo    = (const float*)d_in[9];
    float* out = (float*)d_out;

    cudaFuncSetAttribute(k_fused, cudaFuncAttributeMaxDynamicSharedMemorySize, SMF);

    k_pre<<<1280, 256>>>(msa, mask, gamma, beta, Wa, ba, Wb, bb, Wo);
    k_fused<<<dim3(64, 64), 256, SMF>>>(bo, out);
}

// round 15
// speedup vs baseline: 1.6814x; 1.2154x over previous
#include <cuda_runtime.h>
#include <cuda_fp16.h>
#include <cstdint>

// Problem constants
#define SS_   128
#define NRES  256
#define DD    64
#define HH_   32
#define M_TOT 8192
#define KK2   1024

// ---------------- device scratch (fp16 split; B has hi only) ----------------
__device__ __align__(16) __half g_Ah[M_TOT * SS_];
__device__ __align__(16) __half g_Al[M_TOT * SS_];
__device__ __align__(16) __half g_Bh[M_TOT * SS_];
// Wo^T frag-linear per 16x16 tile (layout validated in R11)
__device__ __align__(16) __half g_Wph[64 * 4 * 256];
__device__ __align__(16) __half g_Wpl[64 * 4 * 256];

__device__ __forceinline__ uint32_t pack_h2(float v0, float v1, float& l0, float& l1) {
    __half h0 = __float2half_rn(v0), h1 = __float2half_rn(v1);
    l0 = v0 - __half2float(h0);
    l1 = v1 - __half2float(h1);
    return (uint32_t)__half_as_ushort(h0) | ((uint32_t)__half_as_ushort(h1) << 16);
}
__device__ __forceinline__ uint32_t pack_h2n(float v0, float v1) {
    __half h0 = __float2half_rn(v0), h1 = __float2half_rn(v1);
    return (uint32_t)__half_as_ushort(h0) | ((uint32_t)__half_as_ushort(h1) << 16);
}

__device__ __forceinline__ void cpa16(void* s, const void* g) {
    uint32_t sa = (uint32_t)__cvta_generic_to_shared(s);
    asm volatile("cp.async.cg.shared.global [%0], [%1], 16;" :: "r"(sa), "l"(g));
}
__device__ __forceinline__ void cpa_commit() {
    asm volatile("cp.async.commit_group;" ::: "memory");
}
template <int N>
__device__ __forceinline__ void cpa_wait() {
    asm volatile("cp.async.wait_group %0;" :: "n"(N) : "memory");
}

#define MMA16816(D, A0, A1, A2, A3, B0, B1) \
    asm volatile("mma.sync.aligned.m16n8k16.row.col.f32.f16.f16.f32 " \
        "{%0,%1,%2,%3}, {%4,%5,%6,%7}, {%8,%9}, {%0,%1,%2,%3};" \
        : "+f"((D)[0]), "+f"((D)[1]), "+f"((D)[2]), "+f"((D)[3]) \
        : "r"(A0), "r"(A1), "r"(A2), "r"(A3), "r"(B0), "r"(B1))

#define LDSM_X4(R0, R1, R2, R3, ADDR) \
    asm volatile("ldmatrix.sync.aligned.m8n8.x4.shared.b16 {%0,%1,%2,%3}, [%4];" \
        : "=r"(R0), "=r"(R1), "=r"(R2), "=r"(R3) : "r"(ADDR))

// ---------------- k_pre: prep (blocks 0-1023) + Wo pack (blocks 1024-1279) ----------------
__global__ void __launch_bounds__(256) k_pre(
    const float* __restrict__ x, const float* __restrict__ mask,
    const float* __restrict__ gamma, const float* __restrict__ beta,
    const float* __restrict__ Wa, const float* __restrict__ ba,
    const float* __restrict__ Wb, const float* __restrict__ bb,
    const float* __restrict__ Wo)
{
    int b = blockIdx.x;
    int tid = threadIdx.x;

    if (b >= 1024) {
        // ---- Wo frag-linear pack (fp16 hi/lo) ----
        int idx = (b - 1024) * 256 + tid;
        int tile = idx >> 8;
        int within = idx & 255;
        int lane = within >> 3, e = within & 7;
        int kt = tile >> 2, nf = tile & 3;
        int n = (lane >> 2) + ((e >> 2) << 3);
        int cc = lane & 3;
        int k = 2 * cc + (e & 1) + (((e >> 1) & 1) << 3);
        float v = Wo[(size_t)(kt * 16 + k) * 64 + nf * 16 + n];
        __half h = __float2half_rn(v);
        g_Wph[idx] = h;
        g_Wpl[idx] = __float2half_rn(v - __half2float(h));
        return;
    }

    // ---- prep: block b -> i = b>>2, s-group sg = b&3 (32 rows) ----
    __shared__ float sx[8][64];
    __shared__ float sa[32][33];
    __shared__ float sb[32][33];
    __shared__ float smask[128];
    __shared__ float sinv;
    int i = b >> 2, sg = b & 3;
    int warp = tid >> 5, lane = tid & 31;

    if (tid < 128) smask[tid] = mask[tid * NRES + i];
    __syncthreads();
    if (tid == 0) {
        float s = 0.f;
        #pragma unroll 8
        for (int t = 0; t < 128; ++t) s += smask[t];
        sinv = 1.0f / fmaxf(s, 1.0f);
    }
    __syncthreads();
    float inv = sinv;

    #pragma unroll
    for (int r = 0; r < 4; ++r) {
        int sl = warp * 4 + r;
        int s = sg * 32 + sl;
        const float* xr = x + ((size_t)s * NRES + i) * DD;
        float v0 = xr[lane], v1 = xr[lane + 32];
        float sum = v0 + v1;
        #pragma unroll
        for (int o = 16; o; o >>= 1) sum += __shfl_xor_sync(~0u, sum, o);
        float mu = sum * (1.0f / 64.0f);
        float d0 = v0 - mu, d1 = v1 - mu;
        float vs = d0 * d0 + d1 * d1;
        #pragma unroll
        for (int o = 16; o; o >>= 1) vs += __shfl_xor_sync(~0u, vs, o);
        float rstd = rsqrtf(vs * (1.0f / 64.0f) + 1e-5f);
        sx[warp][lane]      = d0 * rstd * gamma[lane]      + beta[lane];
        sx[warp][lane + 32] = d1 * rstd * gamma[lane + 32] + beta[lane + 32];
        __syncwarp();

        float m = smask[s];
        float a = ba[lane], bv = bb[lane];
        #pragma unroll
        for (int d = 0; d < 64; ++d) {
            float xv = sx[warp][d];
            a  = fmaf(xv, Wa[d * HH_ + lane], a);
            bv = fmaf(xv, Wb[d * HH_ + lane], bv);
        }
        sa[sl][lane] = a * m * inv;
        sb[sl][lane] = bv * m;
        __syncwarp();
    }
    __syncthreads();

    int h = tid >> 3, j = tid & 7;
    size_t off = ((size_t)i * 32 + h) * SS_ + sg * 32 + j * 4;
    {
        float l0, l1, l2, l3;
        uint32_t h0 = pack_h2(sa[j * 4 + 0][h], sa[j * 4 + 1][h], l0, l1);
        uint32_t h1 = pack_h2(sa[j * 4 + 2][h], sa[j * 4 + 3][h], l2, l3);
        *(uint2*)(g_Ah + off) = make_uint2(h0, h1);
        *(uint2*)(g_Al + off) = make_uint2(pack_h2n(l0, l1), pack_h2n(l2, l3));
    }
    {
        uint32_t h0 = pack_h2n(sb[j * 4 + 0][h], sb[j * 4 + 1][h]);
        uint32_t h1 = pack_h2n(sb[j * 4 + 2][h], sb[j * 4 + 3][h]);
        *(uint2*)(g_Bh + off) = make_uint2(h0, h1);
    }
}

// ===================== FUSED kernel =====================
#define SKC 40
#define STAGE_B (3 * 128 * SKC * 2)   // 30720 B per stage (Ah|Al|Bh)
#define AE_LD 1032
#define SMF 98816

__global__ void __launch_bounds__(256, 2) k_fused(const float* __restrict__ bo,
                                                  float* __restrict__ out) {
    extern __shared__ char smc[];
    int tid = threadIdx.x;
    int wid = tid >> 5, lane = tid & 31;
    int wm = wid & 3, wn = wid >> 2;
    int bm = blockIdx.x, bn = blockIdx.y;
    int g = lane >> 2, cg = lane & 3;
    int lrow  = (lane & 7) + ((lane >> 3) & 1) * 8;
    int lcol8 = (lane >> 4) * 8;

    const __half* gAh = g_Ah + (size_t)bm * 128 * SS_;
    const __half* gAl = g_Al + (size_t)bm * 128 * SS_;
    const __half* gBh = g_Bh + (size_t)bn * 128 * SS_;

    float d1[2][8][4];
    #pragma unroll
    for (int a = 0; a < 2; ++a)
        #pragma unroll
        for (int b = 0; b < 8; ++b)
            #pragma unroll
            for (int e = 0; e < 4; ++e) d1[a][b][e] = 0.f;

    auto load_stage = [&](int stage, int ch) {
        char* base = smc + stage * STAGE_B;
        __half* dAh = (__half*)base;
        __half* dAl = dAh + 128 * SKC;
        __half* dBh = dAl + 128 * SKC;
        int kb = ch * 32;
        #pragma unroll
        for (int it = 0; it < 2; ++it) {
            int idx = it * 256 + tid;
            int row = idx >> 2, seg = idx & 3;
            size_t go = (size_t)row * SS_ + kb + seg * 8;
            int so = row * SKC + seg * 8;
            cpa16(dAh + so, gAh + go);
            cpa16(dAl + so, gAl + go);
            cpa16(dBh + so, gBh + go);
        }
        cpa_commit();
    };

    // ---------------- Phase 1: pipelined mainloop (fp16, 2-product) ----------------
    load_stage(0, 0);
    #pragma unroll
    for (int ch = 0; ch < 4; ++ch) {
        int cur = ch & 1;
        if (ch < 3) load_stage(cur ^ 1, ch + 1);
        if (ch < 3) cpa_wait<1>(); else cpa_wait<0>();
        __syncthreads();

        char* base = smc + cur * STAGE_B;
        __half* sAh = (__half*)base;
        __half* sAl = sAh + 128 * SKC;
        __half* sBh = sAl + 128 * SKC;

        #pragma unroll
        for (int ks = 0; ks < 2; ++ks) {
            int kc = ks * 16 + lcol8;
            uint32_t ah[2][4], al[2][4];
            #pragma unroll
            for (int mf = 0; mf < 2; ++mf) {
                uint32_t adh = (uint32_t)__cvta_generic_to_shared(
                    sAh + (wm * 32 + mf * 16 + lrow) * SKC + kc);
                uint32_t adl = (uint32_t)__cvta_generic_to_shared(
                    sAl + (wm * 32 + mf * 16 + lrow) * SKC + kc);
                LDSM_X4(ah[mf][0], ah[mf][1], ah[mf][2], ah[mf][3], adh);
                LDSM_X4(al[mf][0], al[mf][1], al[mf][2], al[mf][3], adl);
            }
            uint32_t bb[8][2];
            int bnr = (wn * 64) + ((lane >> 4) & 1) * 8 + (lane & 7);
            int bkc = ks * 16 + ((lane >> 3) & 1) * 8;
            #pragma unroll
            for (int q = 0; q < 4; ++q) {
                uint32_t ad = (uint32_t)__cvta_generic_to_shared(
                    sBh + (bnr + q * 16) * SKC + bkc);
                LDSM_X4(bb[2*q][0], bb[2*q][1], bb[2*q+1][0], bb[2*q+1][1], ad);
            }
            #pragma unroll
            for (int nt = 0; nt < 8; ++nt) MMA16816(d1[0][nt], ah[0][0], ah[0][1], ah[0][2], ah[0][3], bb[nt][0], bb[nt][1]);
            #pragma unroll
            for (int nt = 0; nt < 8; ++nt) MMA16816(d1[1][nt], ah[1][0], ah[1][1], ah[1][2], ah[1][3], bb[nt][0], bb[nt][1]);
            #pragma unroll
            for (int nt = 0; nt < 8; ++nt) MMA16816(d1[0][nt], al[0][0], al[0][1], al[0][2], al[0][3], bb[nt][0], bb[nt][1]);
            #pragma unroll
            for (int nt = 0; nt < 8; ++nt) MMA16816(d1[1][nt], al[1][0], al[1][1], al[1][2], al[1][3], bb[nt][0], bb[nt][1]);
        }
        __syncthreads();
    }

    // ---------------- Phase 2: epilogue (fp16 split, 3-product vs Wo) ----------------
    __half* sAe_h = (__half*)smc;
    __half* sAe_l = sAe_h + 16 * AE_LD;
    float* sPart = (float*)(smc + 66048);

    // prefetch Wo ks=0 regs before conversion (hide LDG latency)
    uint4 vh[2][4], vl[2][4];
    {
        int kt0 = wid * 8;
        #pragma unroll
        for (int nf = 0; nf < 4; ++nf) {
            vh[0][nf] = ((const uint4*)g_Wph)[(size_t)(kt0 * 4 + nf) * 32 + lane];
            vl[0][nf] = ((const uint4*)g_Wpl)[(size_t)(kt0 * 4 + nf) * 32 + lane];
        }
    }

    // Phase 2a: direct register conversion -> sAe hi/lo [16][1024]
    {
        #pragma unroll
        for (int mf = 0; mf < 2; ++mf)
            #pragma unroll
            for (int nt = 0; nt < 8; ++nt) {
                int r = wm * 4 + wn * 2 + (nt >> 2);
                int cb = (nt & 3) * 8 + cg * 2;
                #pragma unroll
                for (int rh = 0; rh < 2; ++rh) {
                    float v0 = d1[mf][nt][rh * 2], v1 = d1[mf][nt][rh * 2 + 1];
                    float l0, l1;
                    uint32_t hp = pack_h2(v0, v1, l0, l1);
                    uint32_t lp = pack_h2n(l0, l1);
                    int c = (mf * 16 + g + rh * 8) * 32 + cb;
                    *(uint32_t*)(sAe_h + r * AE_LD + c) = hp;
                    *(uint32_t*)(sAe_l + r * AE_LD + c) = lp;
                }
            }
    }
    __syncthreads();

    // Phase 2b: C16x64 = sAe @ Wo (double-buffered Wo regs, 3 products)
    {
        float d[4][2][4];
        #pragma unroll
        for (int a = 0; a < 4; ++a)
            #pragma unroll
            for (int b = 0; b < 2; ++b)
                #pragma unroll
                for (int e = 0; e < 4; ++e) d[a][b][e] = 0.f;

        #pragma unroll
        for (int ks = 0; ks < 8; ++ks) {
            int cur = ks & 1;
            if (ks < 7) {
                int ktn = wid * 8 + ks + 1;
                #pragma unroll
                for (int nf = 0; nf < 4; ++nf) {
                    vh[cur ^ 1][nf] = ((const uint4*)g_Wph)[(size_t)(ktn * 4 + nf) * 32 + lane];
                    vl[cur ^ 1][nf] = ((const uint4*)g_Wpl)[(size_t)(ktn * 4 + nf) * 32 + lane];
                }
            }
            int kk = (wid * 8 + ks) * 16;
            uint32_t ah0, ah1, ah2, ah3, al0, al1, al2, al3;
            uint32_t adh = (uint32_t)__cvta_generic_to_shared(sAe_h + lrow * AE_LD + kk + lcol8);
            uint32_t adl = (uint32_t)__cvta_generic_to_shared(sAe_l + lrow * AE_LD + kk + lcol8);
            LDSM_X4(ah0, ah1, ah2, ah3, adh);
            LDSM_X4(al0, al1, al2, al3, adl);
            #pragma unroll
            for (int nf = 0; nf < 4; ++nf) {
                uint4 wh = vh[cur][nf], wl = vl[cur][nf];
                MMA16816(d[nf][0], ah0, ah1, ah2, ah3, wh.x, wh.y);
                MMA16816(d[nf][1], ah0, ah1, ah2, ah3, wh.z, wh.w);
                MMA16816(d[nf][0], al0, al1, al2, al3, wh.x, wh.y);
                MMA16816(d[nf][1], al0, al1, al2, al3, wh.z, wh.w);
                MMA16816(d[nf][0], ah0, ah1, ah2, ah3, wl.x, wl.y);
                MMA16816(d[nf][1], ah0, ah1, ah2, ah3, wl.z, wl.w);
            }
        }
        __syncthreads();

        #pragma unroll
        for (int nf = 0; nf < 4; ++nf)
            #pragma unroll
            for (int blk = 0; blk < 2; ++blk) {
                int col = nf * 16 + blk * 8 + cg * 2;
                float* p0 = sPart + wid * 1024 + g * 64 + col;
                p0[0] = d[nf][blk][0]; p0[1] = d[nf][blk][1];
                float* p1 = sPart + wid * 1024 + (g + 8) * 64 + col;
                p1[0] = d[nf][blk][2]; p1[1] = d[nf][blk][3];
            }
    }
    __syncthreads();

    // Phase 2c: reduce 8 partials, +bo, store
    {
        int row = tid >> 4;
        int p4  = (tid & 15) * 4;
        float4 s = *(float4*)(sPart + row * 64 + p4);
        #pragma unroll
        for (int w = 1; w < 8; ++w) {
            float4 v = *(float4*)(sPart + w * 1024 + row * 64 + p4);
            s.x += v.x; s.y += v.y; s.z += v.z; s.w += v.w;
        }
        float4 bv = __ldg((const float4*)(bo + p4));
        s.x += bv.x; s.y += bv.y; s.z += bv.z; s.w += bv.w;
        size_t rg = (size_t)(bm * 4 + (row >> 2)) * 256 + bn * 4 + (row & 3);
        *(float4*)(out + rg * 64 + p4) = s;
    }
}

extern "C" void kernel_launch(void* const* d_in, const int* in_sizes, int n_in,
                              void* d_out, int out_size) {
    const float* msa   = (const float*)d_in[0];
    const float* mask  = (const float*)d_in[1];
    const float* gamma = (const float*)d_in[2];
    const float* beta  = (const float*)d_in[3];
    const float* Wa    = (const float*)d_in[4];
    const float* ba    = (const float*)d_in[5];
    const float* Wb    = (const float*)d_in[6];
    const float* bb    = (const float*)d_in[7];
    const float* Wo    = (const float*)d_in[8];
    const float* bo    = (const float*)d_in[9];
    float* out = (float*)d_out;

    cudaFuncSetAttribute(k_fused, cudaFuncAttributeMaxDynamicSharedMemorySize, SMF);

    k_pre<<<1280, 256>>>(msa, mask, gamma, beta, Wa, ba, Wb, bb, Wo);
    k_fused<<<dim3(64, 64), 256, SMF>>>(bo, out);
}

// round 16
// speedup vs baseline: 1.9379x; 1.1526x over previous
#include <cuda_runtime.h>
#include <cuda_fp16.h>
#include <cstdint>

// Problem constants
#define SS_   128
#define NRES  256
#define DD    64
#define HH_   32
#define M_TOT 8192
#define KK2   1024

// ---------------- device scratch (fp16; mainloop single-product: A,B hi only) ----------------
__device__ __align__(16) __half g_Ah[M_TOT * SS_];
__device__ __align__(16) __half g_Bh[M_TOT * SS_];
// Wo^T frag-linear per 16x16 tile (layout validated in R11)
__device__ __align__(16) __half g_Wph[64 * 4 * 256];
__device__ __align__(16) __half g_Wpl[64 * 4 * 256];

__device__ __forceinline__ uint32_t pack_h2(float v0, float v1, float& l0, float& l1) {
    __half h0 = __float2half_rn(v0), h1 = __float2half_rn(v1);
    l0 = v0 - __half2float(h0);
    l1 = v1 - __half2float(h1);
    return (uint32_t)__half_as_ushort(h0) | ((uint32_t)__half_as_ushort(h1) << 16);
}
__device__ __forceinline__ uint32_t pack_h2n(float v0, float v1) {
    __half h0 = __float2half_rn(v0), h1 = __float2half_rn(v1);
    return (uint32_t)__half_as_ushort(h0) | ((uint32_t)__half_as_ushort(h1) << 16);
}

__device__ __forceinline__ void cpa16(void* s, const void* g) {
    uint32_t sa = (uint32_t)__cvta_generic_to_shared(s);
    asm volatile("cp.async.cg.shared.global [%0], [%1], 16;" :: "r"(sa), "l"(g));
}
__device__ __forceinline__ void cpa_commit() {
    asm volatile("cp.async.commit_group;" ::: "memory");
}
template <int N>
__device__ __forceinline__ void cpa_wait() {
    asm volatile("cp.async.wait_group %0;" :: "n"(N) : "memory");
}

#define MMA16816(D, A0, A1, A2, A3, B0, B1) \
    asm volatile("mma.sync.aligned.m16n8k16.row.col.f32.f16.f16.f32 " \
        "{%0,%1,%2,%3}, {%4,%5,%6,%7}, {%8,%9}, {%0,%1,%2,%3};" \
        : "+f"((D)[0]), "+f"((D)[1]), "+f"((D)[2]), "+f"((D)[3]) \
        : "r"(A0), "r"(A1), "r"(A2), "r"(A3), "r"(B0), "r"(B1))

#define LDSM_X4(R0, R1, R2, R3, ADDR) \
    asm volatile("ldmatrix.sync.aligned.m8n8.x4.shared.b16 {%0,%1,%2,%3}, [%4];" \
        : "=r"(R0), "=r"(R1), "=r"(R2), "=r"(R3) : "r"(ADDR))

// ---------------- k_pre: prep (blocks 0-1023) + Wo pack (blocks 1024-1279) ----------------
__global__ void __launch_bounds__(256) k_pre(
    const float* __restrict__ x, const float* __restrict__ mask,
    const float* __restrict__ gamma, const float* __restrict__ beta,
    const float* __restrict__ Wa, const float* __restrict__ ba,
    const float* __restrict__ Wb, const float* __restrict__ bb,
    const float* __restrict__ Wo)
{
    int b = blockIdx.x;
    int tid = threadIdx.x;

    if (b >= 1024) {
        // ---- Wo frag-linear pack (fp16 hi/lo) ----
        int idx = (b - 1024) * 256 + tid;
        int tile = idx >> 8;
        int within = idx & 255;
        int lane = within >> 3, e = within & 7;
        int kt = tile >> 2, nf = tile & 3;
        int n = (lane >> 2) + ((e >> 2) << 3);
        int cc = lane & 3;
        int k = 2 * cc + (e & 1) + (((e >> 1) & 1) << 3);
        float v = Wo[(size_t)(kt * 16 + k) * 64 + nf * 16 + n];
        __half h = __float2half_rn(v);
        g_Wph[idx] = h;
        g_Wpl[idx] = __float2half_rn(v - __half2float(h));
        return;
    }

    // ---- prep: block b -> i = b>>2, s-group sg = b&3 (32 rows) ----
    __shared__ float sx[8][64];
    __shared__ float sa[32][33];
    __shared__ float sb[32][33];
    __shared__ float smask[128];
    __shared__ float sinv;
    int i = b >> 2, sg = b & 3;
    int warp = tid >> 5, lane = tid & 31;

    if (tid < 128) smask[tid] = mask[tid * NRES + i];
    __syncthreads();
    if (tid == 0) {
        float s = 0.f;
        #pragma unroll 8
        for (int t = 0; t < 128; ++t) s += smask[t];
        sinv = 1.0f / fmaxf(s, 1.0f);
    }
    __syncthreads();
    float inv = sinv;

    #pragma unroll
    for (int r = 0; r < 4; ++r) {
        int sl = warp * 4 + r;
        int s = sg * 32 + sl;
        const float* xr = x + ((size_t)s * NRES + i) * DD;
        float v0 = xr[lane], v1 = xr[lane + 32];
        float sum = v0 + v1;
        #pragma unroll
        for (int o = 16; o; o >>= 1) sum += __shfl_xor_sync(~0u, sum, o);
        float mu = sum * (1.0f / 64.0f);
        float d0 = v0 - mu, d1 = v1 - mu;
        float vs = d0 * d0 + d1 * d1;
        #pragma unroll
        for (int o = 16; o; o >>= 1) vs += __shfl_xor_sync(~0u, vs, o);
        float rstd = rsqrtf(vs * (1.0f / 64.0f) + 1e-5f);
        sx[warp][lane]      = d0 * rstd * gamma[lane]      + beta[lane];
        sx[warp][lane + 32] = d1 * rstd * gamma[lane + 32] + beta[lane + 32];
        __syncwarp();

        float m = smask[s];
        float a = ba[lane], bv = bb[lane];
        #pragma unroll
        for (int d = 0; d < 64; ++d) {
            float xv = sx[warp][d];
            a  = fmaf(xv, Wa[d * HH_ + lane], a);
            bv = fmaf(xv, Wb[d * HH_ + lane], bv);
        }
        sa[sl][lane] = a * m * inv;
        sb[sl][lane] = bv * m;
        __syncwarp();
    }
    __syncthreads();

    int h = tid >> 3, j = tid & 7;
    size_t off = ((size_t)i * 32 + h) * SS_ + sg * 32 + j * 4;
    {
        uint32_t h0 = pack_h2n(sa[j * 4 + 0][h], sa[j * 4 + 1][h]);
        uint32_t h1 = pack_h2n(sa[j * 4 + 2][h], sa[j * 4 + 3][h]);
        *(uint2*)(g_Ah + off) = make_uint2(h0, h1);
    }
    {
        uint32_t h0 = pack_h2n(sb[j * 4 + 0][h], sb[j * 4 + 1][h]);
        uint32_t h1 = pack_h2n(sb[j * 4 + 2][h], sb[j * 4 + 3][h]);
        *(uint2*)(g_Bh + off) = make_uint2(h0, h1);
    }
}

// ===================== FUSED kernel =====================
#define SKC 40
#define STAGE_B (2 * 128 * SKC * 2)   // 20480 B per stage (Ah|Bh)
#define AE_LD 1032
#define SMF 98816

__global__ void __launch_bounds__(256, 2) k_fused(const float* __restrict__ bo,
                                                  float* __restrict__ out) {
    extern __shared__ char smc[];
    int tid = threadIdx.x;
    int wid = tid >> 5, lane = tid & 31;
    int wm = wid & 3, wn = wid >> 2;
    int bm = blockIdx.x, bn = blockIdx.y;
    int g = lane >> 2, cg = lane & 3;
    int lrow  = (lane & 7) + ((lane >> 3) & 1) * 8;
    int lcol8 = (lane >> 4) * 8;

    const __half* gAh = g_Ah + (size_t)bm * 128 * SS_;
    const __half* gBh = g_Bh + (size_t)bn * 128 * SS_;

    float d1[2][8][4];
    #pragma unroll
    for (int a = 0; a < 2; ++a)
        #pragma unroll
        for (int b = 0; b < 8; ++b)
            #pragma unroll
            for (int e = 0; e < 4; ++e) d1[a][b][e] = 0.f;

    auto load_stage = [&](int stage, int ch) {
        char* base = smc + stage * STAGE_B;
        __half* dAh = (__half*)base;
        __half* dBh = dAh + 128 * SKC;
        int kb = ch * 32;
        #pragma unroll
        for (int it = 0; it < 2; ++it) {
            int idx = it * 256 + tid;
            int row = idx >> 2, seg = idx & 3;
            size_t go = (size_t)row * SS_ + kb + seg * 8;
            int so = row * SKC + seg * 8;
            cpa16(dAh + so, gAh + go);
            cpa16(dBh + so, gBh + go);
        }
        cpa_commit();
    };

    // ---------------- Phase 1: pipelined mainloop (fp16, single product) ----------------
    load_stage(0, 0);
    #pragma unroll
    for (int ch = 0; ch < 4; ++ch) {
        int cur = ch & 1;
        if (ch < 3) load_stage(cur ^ 1, ch + 1);
        if (ch < 3) cpa_wait<1>(); else cpa_wait<0>();
        __syncthreads();

        char* base = smc + cur * STAGE_B;
        __half* sAh = (__half*)base;
        __half* sBh = sAh + 128 * SKC;

        #pragma unroll
        for (int ks = 0; ks < 2; ++ks) {
            int kc = ks * 16 + lcol8;
            uint32_t ah[2][4];
            #pragma unroll
            for (int mf = 0; mf < 2; ++mf) {
                uint32_t adh = (uint32_t)__cvta_generic_to_shared(
                    sAh + (wm * 32 + mf * 16 + lrow) * SKC + kc);
                LDSM_X4(ah[mf][0], ah[mf][1], ah[mf][2], ah[mf][3], adh);
            }
            uint32_t bb[8][2];
            int bnr = (wn * 64) + ((lane >> 4) & 1) * 8 + (lane & 7);
            int bkc = ks * 16 + ((lane >> 3) & 1) * 8;
            #pragma unroll
            for (int q = 0; q < 4; ++q) {
                uint32_t ad = (uint32_t)__cvta_generic_to_shared(
                    sBh + (bnr + q * 16) * SKC + bkc);
                LDSM_X4(bb[2*q][0], bb[2*q][1], bb[2*q+1][0], bb[2*q+1][1], ad);
            }
            #pragma unroll
            for (int nt = 0; nt < 8; ++nt) MMA16816(d1[0][nt], ah[0][0], ah[0][1], ah[0][2], ah[0][3], bb[nt][0], bb[nt][1]);
            #pragma unroll
            for (int nt = 0; nt < 8; ++nt) MMA16816(d1[1][nt], ah[1][0], ah[1][1], ah[1][2], ah[1][3], bb[nt][0], bb[nt][1]);
        }
        __syncthreads();
    }

    // ---------------- Phase 2: epilogue (fp16 split, 3-product vs Wo) ----------------
    __half* sAe_h = (__half*)smc;
    __half* sAe_l = sAe_h + 16 * AE_LD;
    float* sPart = (float*)(smc + 66048);

    // prefetch Wo ks=0 regs before conversion (hide LDG latency)
    uint4 vh[2][4], vl[2][4];
    {
        int kt0 = wid * 8;
        #pragma unroll
        for (int nf = 0; nf < 4; ++nf) {
            vh[0][nf] = ((const uint4*)g_Wph)[(size_t)(kt0 * 4 + nf) * 32 + lane];
            vl[0][nf] = ((const uint4*)g_Wpl)[(size_t)(kt0 * 4 + nf) * 32 + lane];
        }
    }

    // Phase 2a: direct register conversion -> sAe hi/lo [16][1024]
    {
        #pragma unroll
        for (int mf = 0; mf < 2; ++mf)
            #pragma unroll
            for (int nt = 0; nt < 8; ++nt) {
                int r = wm * 4 + wn * 2 + (nt >> 2);
                int cb = (nt & 3) * 8 + cg * 2;
                #pragma unroll
                for (int rh = 0; rh < 2; ++rh) {
                    float v0 = d1[mf][nt][rh * 2], v1 = d1[mf][nt][rh * 2 + 1];
                    float l0, l1;
                    uint32_t hp = pack_h2(v0, v1, l0, l1);
                    uint32_t lp = pack_h2n(l0, l1);
                    int c = (mf * 16 + g + rh * 8) * 32 + cb;
                    *(uint32_t*)(sAe_h + r * AE_LD + c) = hp;
                    *(uint32_t*)(sAe_l + r * AE_LD + c) = lp;
                }
            }
    }
    __syncthreads();

    // Phase 2b: C16x64 = sAe @ Wo (double-buffered Wo regs, 3 products)
    {
        float d[4][2][4];
        #pragma unroll
        for (int a = 0; a < 4; ++a)
            #pragma unroll
            for (int b = 0; b < 2; ++b)
                #pragma unroll
                for (int e = 0; e < 4; ++e) d[a][b][e] = 0.f;

        #pragma unroll
        for (int ks = 0; ks < 8; ++ks) {
            int cur = ks & 1;
            if (ks < 7) {
                int ktn = wid * 8 + ks + 1;
                #pragma unroll
                for (int nf = 0; nf < 4; ++nf) {
                    vh[cur ^ 1][nf] = ((const uint4*)g_Wph)[(size_t)(ktn * 4 + nf) * 32 + lane];
                    vl[cur ^ 1][nf] = ((const uint4*)g_Wpl)[(size_t)(ktn * 4 + nf) * 32 + lane];
                }
            }
            int kk = (wid * 8 + ks) * 16;
            uint32_t ah0, ah1, ah2, ah3, al0, al1, al2, al3;
            uint32_t adh = (uint32_t)__cvta_generic_to_shared(sAe_h + lrow * AE_LD + kk + lcol8);
            uint32_t adl = (uint32_t)__cvta_generic_to_shared(sAe_l + lrow * AE_LD + kk + lcol8);
            LDSM_X4(ah0, ah1, ah2, ah3, adh);
            LDSM_X4(al0, al1, al2, al3, adl);
            #pragma unroll
            for (int nf = 0; nf < 4; ++nf) {
                uint4 wh = vh[cur][nf], wl = vl[cur][nf];
                MMA16816(d[nf][0], ah0, ah1, ah2, ah3, wh.x, wh.y);
                MMA16816(d[nf][1], ah0, ah1, ah2, ah3, wh.z, wh.w);
                MMA16816(d[nf][0], al0, al1, al2, al3, wh.x, wh.y);
                MMA16816(d[nf][1], al0, al1, al2, al3, wh.z, wh.w);
                MMA16816(d[nf][0], ah0, ah1, ah2, ah3, wl.x, wl.y);
                MMA16816(d[nf][1], ah0, ah1, ah2, ah3, wl.z, wl.w);
            }
        }
        __syncthreads();

        #pragma unroll
        for (int nf = 0; nf < 4; ++nf)
            #pragma unroll
            for (int blk = 0; blk < 2; ++blk) {
                int col = nf * 16 + blk * 8 + cg * 2;
                float* p0 = sPart + wid * 1024 + g * 64 + col;
                p0[0] = d[nf][blk][0]; p0[1] = d[nf][blk][1];
                float* p1 = sPart + wid * 1024 + (g + 8) * 64 + col;
                p1[0] = d[nf][blk][2]; p1[1] = d[nf][blk][3];
            }
    }
    __syncthreads();

    // Phase 2c: reduce 8 partials, +bo, store
    {
        int row = tid >> 4;
        int p4  = (tid & 15) * 4;
        float4 s = *(float4*)(sPart + row * 64 + p4);
        #pragma unroll
        for (int w = 1; w < 8; ++w) {
            float4 v = *(float4*)(sPart + w * 1024 + row * 64 + p4);
            s.x += v.x; s.y += v.y; s.z += v.z; s.w += v.w;
        }
        float4 bv = __ldg((const float4*)(bo + p4));
        s.x += bv.x; s.y += bv.y; s.z += bv.z; s.w += bv.w;
        size_t rg = (size_t)(bm * 4 + (row >> 2)) * 256 + bn * 4 + (row & 3);
        *(float4*)(out + rg * 64 + p4) = s;
    }
}

extern "C" void kernel_launch(void* const* d_in, const int* in_sizes, int n_in,
                              void* d_out, int out_size) {
    const float* msa   = (const float*)d_in[0];
    const float* mask  = (const float*)d_in[1];
    const float* gamma = (const float*)d_in[2];
    const float* beta  = (const float*)d_in[3];
    const float* Wa    = (const float*)d_in[4];
    const float* ba    = (const float*)d_in[5];
    const float* Wb    = (const float*)d_in[6];
    const float* bb    = (const float*)d_in[7];
    const float* Wo    = (const float*)d_in[8];
    const float* bo    = (const float*)d_in[9];
    float* out = (float*)d_out;

    cudaFuncSetAttribute(k_fused, cudaFuncAttributeMaxDynamicSharedMemorySize, SMF);

    k_pre<<<1280, 256>>>(msa, mask, gamma, beta, Wa, ba, Wb, bb, Wo);
    k_fused<<<dim3(64, 64), 256, SMF>>>(bo, out);
}

// round 17
// speedup vs baseline: 2.5485x; 1.3151x over previous
#include <cuda_runtime.h>
#include <cuda_fp16.h>
#include <cstdint>

// Problem constants
#define SS_   128
#define NRES  256
#define DD    64
#define HH_   32
#define M_TOT 8192
#define KK2   1024

// ---------------- device scratch (fp16 hi-only everywhere) ----------------
__device__ __align__(16) __half g_Ah[M_TOT * SS_];
__device__ __align__(16) __half g_Bh[M_TOT * SS_];
// Wo^T frag-linear per 16x16 tile (layout validated in R11), hi only
__device__ __align__(16) __half g_Wph[64 * 4 * 256];

__device__ __forceinline__ uint32_t pack_h2n(float v0, float v1) {
    __half h0 = __float2half_rn(v0), h1 = __float2half_rn(v1);
    return (uint32_t)__half_as_ushort(h0) | ((uint32_t)__half_as_ushort(h1) << 16);
}

__device__ __forceinline__ void cpa16(void* s, const void* g) {
    uint32_t sa = (uint32_t)__cvta_generic_to_shared(s);
    asm volatile("cp.async.cg.shared.global [%0], [%1], 16;" :: "r"(sa), "l"(g));
}
__device__ __forceinline__ void cpa_commit() {
    asm volatile("cp.async.commit_group;" ::: "memory");
}
template <int N>
__device__ __forceinline__ void cpa_wait() {
    asm volatile("cp.async.wait_group %0;" :: "n"(N) : "memory");
}

#define MMA16816(D, A0, A1, A2, A3, B0, B1) \
    asm volatile("mma.sync.aligned.m16n8k16.row.col.f32.f16.f16.f32 " \
        "{%0,%1,%2,%3}, {%4,%5,%6,%7}, {%8,%9}, {%0,%1,%2,%3};" \
        : "+f"((D)[0]), "+f"((D)[1]), "+f"((D)[2]), "+f"((D)[3]) \
        : "r"(A0), "r"(A1), "r"(A2), "r"(A3), "r"(B0), "r"(B1))

#define LDSM_X4(R0, R1, R2, R3, ADDR) \
    asm volatile("ldmatrix.sync.aligned.m8n8.x4.shared.b16 {%0,%1,%2,%3}, [%4];" \
        : "=r"(R0), "=r"(R1), "=r"(R2), "=r"(R3) : "r"(ADDR))

// ---------------- k_pre: prep (blocks 0-1023) + Wo pack (blocks 1024-1279) ----------------
__global__ void __launch_bounds__(256) k_pre(
    const float* __restrict__ x, const float* __restrict__ mask,
    const float* __restrict__ gamma, const float* __restrict__ beta,
    const float* __restrict__ Wa, const float* __restrict__ ba,
    const float* __restrict__ Wb, const float* __restrict__ bb,
    const float* __restrict__ Wo)
{
    int b = blockIdx.x;
    int tid = threadIdx.x;

    if (b >= 1024) {
        // ---- Wo frag-linear pack (fp16 hi) ----
        int idx = (b - 1024) * 256 + tid;
        int tile = idx >> 8;
        int within = idx & 255;
        int lane = within >> 3, e = within & 7;
        int kt = tile >> 2, nf = tile & 3;
        int n = (lane >> 2) + ((e >> 2) << 3);
        int cc = lane & 3;
        int k = 2 * cc + (e & 1) + (((e >> 1) & 1) << 3);
        float v = Wo[(size_t)(kt * 16 + k) * 64 + nf * 16 + n];
        g_Wph[idx] = __float2half_rn(v);
        return;
    }

    // ---- prep: block b -> i = b>>2, s-group sg = b&3 (32 rows) ----
    __shared__ float sx[8][64];
    __shared__ float sa[32][33];
    __shared__ float sb[32][33];
    __shared__ float smask[128];
    __shared__ float sinv;
    int i = b >> 2, sg = b & 3;
    int warp = tid >> 5, lane = tid & 31;

    if (tid < 128) smask[tid] = mask[tid * NRES + i];
    __syncthreads();
    if (tid == 0) {
        float s = 0.f;
        #pragma unroll 8
        for (int t = 0; t < 128; ++t) s += smask[t];
        sinv = 1.0f / fmaxf(s, 1.0f);
    }
    __syncthreads();
    float inv = sinv;

    #pragma unroll
    for (int r = 0; r < 4; ++r) {
        int sl = warp * 4 + r;
        int s = sg * 32 + sl;
        const float* xr = x + ((size_t)s * NRES + i) * DD;
        float v0 = xr[lane], v1 = xr[lane + 32];
        float sum = v0 + v1;
        #pragma unroll
        for (int o = 16; o; o >>= 1) sum += __shfl_xor_sync(~0u, sum, o);
        float mu = sum * (1.0f / 64.0f);
        float d0 = v0 - mu, d1 = v1 - mu;
        float vs = d0 * d0 + d1 * d1;
        #pragma unroll
        for (int o = 16; o; o >>= 1) vs += __shfl_xor_sync(~0u, vs, o);
        float rstd = rsqrtf(vs * (1.0f / 64.0f) + 1e-5f);
        sx[warp][lane]      = d0 * rstd * gamma[lane]      + beta[lane];
        sx[warp][lane + 32] = d1 * rstd * gamma[lane + 32] + beta[lane + 32];
        __syncwarp();

        float m = smask[s];
        float a = ba[lane], bv = bb[lane];
        #pragma unroll
        for (int d = 0; d < 64; ++d) {
            float xv = sx[warp][d];
            a  = fmaf(xv, Wa[d * HH_ + lane], a);
            bv = fmaf(xv, Wb[d * HH_ + lane], bv);
        }
        sa[sl][lane] = a * m * inv;
        sb[sl][lane] = bv * m;
        __syncwarp();
    }
    __syncthreads();

    int h = tid >> 3, j = tid & 7;
    size_t off = ((size_t)i * 32 + h) * SS_ + sg * 32 + j * 4;
    {
        uint32_t h0 = pack_h2n(sa[j * 4 + 0][h], sa[j * 4 + 1][h]);
        uint32_t h1 = pack_h2n(sa[j * 4 + 2][h], sa[j * 4 + 3][h]);
        *(uint2*)(g_Ah + off) = make_uint2(h0, h1);
    }
    {
        uint32_t h0 = pack_h2n(sb[j * 4 + 0][h], sb[j * 4 + 1][h]);
        uint32_t h1 = pack_h2n(sb[j * 4 + 2][h], sb[j * 4 + 3][h]);
        *(uint2*)(g_Bh + off) = make_uint2(h0, h1);
    }
}

// ===================== FUSED kernel =====================
#define SKC 40
#define STAGE_B (2 * 128 * SKC * 2)   // 20480 B per stage (Ah|Bh)
#define AE_LD 1032
// smem: mainloop 2 stages x 20480 = 40960
//       epilogue sAe_h [0,33024) | sPart [33024,65792)
#define SMF 66048

__global__ void __launch_bounds__(256, 2) k_fused(const float* __restrict__ bo,
                                                  float* __restrict__ out) {
    extern __shared__ char smc[];
    int tid = threadIdx.x;
    int wid = tid >> 5, lane = tid & 31;
    int wm = wid & 3, wn = wid >> 2;
    int bm = blockIdx.x, bn = blockIdx.y;
    int g = lane >> 2, cg = lane & 3;
    int lrow  = (lane & 7) + ((lane >> 3) & 1) * 8;
    int lcol8 = (lane >> 4) * 8;

    const __half* gAh = g_Ah + (size_t)bm * 128 * SS_;
    const __half* gBh = g_Bh + (size_t)bn * 128 * SS_;

    float d1[2][8][4];
    #pragma unroll
    for (int a = 0; a < 2; ++a)
        #pragma unroll
        for (int b = 0; b < 8; ++b)
            #pragma unroll
            for (int e = 0; e < 4; ++e) d1[a][b][e] = 0.f;

    auto load_stage = [&](int stage, int ch) {
        char* base = smc + stage * STAGE_B;
        __half* dAh = (__half*)base;
        __half* dBh = dAh + 128 * SKC;
        int kb = ch * 32;
        #pragma unroll
        for (int it = 0; it < 2; ++it) {
            int idx = it * 256 + tid;
            int row = idx >> 2, seg = idx & 3;
            size_t go = (size_t)row * SS_ + kb + seg * 8;
            int so = row * SKC + seg * 8;
            cpa16(dAh + so, gAh + go);
            cpa16(dBh + so, gBh + go);
        }
        cpa_commit();
    };

    // ---------------- Phase 1: pipelined mainloop (fp16, single product) ----------------
    load_stage(0, 0);
    #pragma unroll
    for (int ch = 0; ch < 4; ++ch) {
        int cur = ch & 1;
        if (ch < 3) load_stage(cur ^ 1, ch + 1);
        if (ch < 3) cpa_wait<1>(); else cpa_wait<0>();
        __syncthreads();

        char* base = smc + cur * STAGE_B;
        __half* sAh = (__half*)base;
        __half* sBh = sAh + 128 * SKC;

        #pragma unroll
        for (int ks = 0; ks < 2; ++ks) {
            int kc = ks * 16 + lcol8;
            uint32_t ah[2][4];
            #pragma unroll
            for (int mf = 0; mf < 2; ++mf) {
                uint32_t adh = (uint32_t)__cvta_generic_to_shared(
                    sAh + (wm * 32 + mf * 16 + lrow) * SKC + kc);
                LDSM_X4(ah[mf][0], ah[mf][1], ah[mf][2], ah[mf][3], adh);
            }
            uint32_t bb[8][2];
            int bnr = (wn * 64) + ((lane >> 4) & 1) * 8 + (lane & 7);
            int bkc = ks * 16 + ((lane >> 3) & 1) * 8;
            #pragma unroll
            for (int q = 0; q < 4; ++q) {
                uint32_t ad = (uint32_t)__cvta_generic_to_shared(
                    sBh + (bnr + q * 16) * SKC + bkc);
                LDSM_X4(bb[2*q][0], bb[2*q][1], bb[2*q+1][0], bb[2*q+1][1], ad);
            }
            #pragma unroll
            for (int nt = 0; nt < 8; ++nt) MMA16816(d1[0][nt], ah[0][0], ah[0][1], ah[0][2], ah[0][3], bb[nt][0], bb[nt][1]);
            #pragma unroll
            for (int nt = 0; nt < 8; ++nt) MMA16816(d1[1][nt], ah[1][0], ah[1][1], ah[1][2], ah[1][3], bb[nt][0], bb[nt][1]);
        }
        __syncthreads();
    }

    // ---------------- Phase 2: epilogue (pure fp16: Ch @ Wh) ----------------
    __half* sAe_h = (__half*)smc;
    float* sPart = (float*)(smc + 33024);

    // prefetch Wo ks=0 regs before conversion (hide LDG latency)
    uint4 vh[2][4];
    {
        int kt0 = wid * 8;
        #pragma unroll
        for (int nf = 0; nf < 4; ++nf)
            vh[0][nf] = ((const uint4*)g_Wph)[(size_t)(kt0 * 4 + nf) * 32 + lane];
    }

    // Phase 2a: direct register conversion -> sAe_h [16][1024]
    {
        #pragma unroll
        for (int mf = 0; mf < 2; ++mf)
            #pragma unroll
            for (int nt = 0; nt < 8; ++nt) {
                int r = wm * 4 + wn * 2 + (nt >> 2);
                int cb = (nt & 3) * 8 + cg * 2;
                #pragma unroll
                for (int rh = 0; rh < 2; ++rh) {
                    uint32_t hp = pack_h2n(d1[mf][nt][rh * 2], d1[mf][nt][rh * 2 + 1]);
                    int c = (mf * 16 + g + rh * 8) * 32 + cb;
                    *(uint32_t*)(sAe_h + r * AE_LD + c) = hp;
                }
            }
    }
    __syncthreads();

    // Phase 2b: C16x64 = sAe_h @ Wo_h (double-buffered Wo regs)
    {
        float d[4][2][4];
        #pragma unroll
        for (int a = 0; a < 4; ++a)
            #pragma unroll
            for (int b = 0; b < 2; ++b)
                #pragma unroll
                for (int e = 0; e < 4; ++e) d[a][b][e] = 0.f;

        #pragma unroll
        for (int ks = 0; ks < 8; ++ks) {
            int cur = ks & 1;
            if (ks < 7) {
                int ktn = wid * 8 + ks + 1;
                #pragma unroll
                for (int nf = 0; nf < 4; ++nf)
                    vh[cur ^ 1][nf] = ((const uint4*)g_Wph)[(size_t)(ktn * 4 + nf) * 32 + lane];
            }
            int kk = (wid * 8 + ks) * 16;
            uint32_t ah0, ah1, ah2, ah3;
            uint32_t adh = (uint32_t)__cvta_generic_to_shared(sAe_h + lrow * AE_LD + kk + lcol8);
            LDSM_X4(ah0, ah1, ah2, ah3, adh);
            #pragma unroll
            for (int nf = 0; nf < 4; ++nf) {
                uint4 wh = vh[cur][nf];
                MMA16816(d[nf][0], ah0, ah1, ah2, ah3, wh.x, wh.y);
                MMA16816(d[nf][1], ah0, ah1, ah2, ah3, wh.z, wh.w);
            }
        }
        __syncthreads();

        #pragma unroll
        for (int nf = 0; nf < 4; ++nf)
            #pragma unroll
            for (int blk = 0; blk < 2; ++blk) {
                int col = nf * 16 + blk * 8 + cg * 2;
                float* p0 = sPart + wid * 1024 + g * 64 + col;
                p0[0] = d[nf][blk][0]; p0[1] = d[nf][blk][1];
                float* p1 = sPart + wid * 1024 + (g + 8) * 64 + col;
                p1[0] = d[nf][blk][2]; p1[1] = d[nf][blk][3];
            }
    }
    __syncthreads();

    // Phase 2c: reduce 8 partials, +bo, store
    {
        int row = tid >> 4;
        int p4  = (tid & 15) * 4;
        float4 s = *(float4*)(sPart + row * 64 + p4);
        #pragma unroll
        for (int w = 1; w < 8; ++w) {
            float4 v = *(float4*)(sPart + w * 1024 + row * 64 + p4);
            s.x += v.x; s.y += v.y; s.z += v.z; s.w += v.w;
        }
        float4 bv = __ldg((const float4*)(bo + p4));
        s.x += bv.x; s.y += bv.y; s.z += bv.z; s.w += bv.w;
        size_t rg = (size_t)(bm * 4 + (row >> 2)) * 256 + bn * 4 + (row & 3);
        *(float4*)(out + rg * 64 + p4) = s;
    }
}

extern "C" void kernel_launch(void* const* d_in, const int* in_sizes, int n_in,
                              void* d_out, int out_size) {
    const float* msa   = (const float*)d_in[0];
    const float* mask  = (const float*)d_in[1];
    const float* gamma = (const float*)d_in[2];
    const float* beta  = (const float*)d_in[3];
    const float* Wa    = (const float*)d_in[4];
    const float* ba    = (const float*)d_in[5];
    const float* Wb    = (const float*)d_in[6];
    const float* bb    = (const float*)d_in[7];
    const float* Wo    = (const float*)d_in[8];
    const float* bo    = (const float*)d_in[9];
    float* out = (float*)d_out;

    cudaFuncSetAttribute(k_fused, cudaFuncAttributeMaxDynamicSharedMemorySize, SMF);

    k_pre<<<1280, 256>>>(msa, mask, gamma, beta, Wa, ba, Wb, bb, Wo);
    k_fused<<<dim3(64, 64), 256, SMF>>>(bo, out);
}